// round 8
// baseline (speedup 1.0000x reference)
#include <cuda_runtime.h>
#include <cuda_bf16.h>
#include <math.h>
#include <stdint.h>

#define B 32
#define C 512
#define Q 128
#define D 768
#define OD (4*D)
#define NEGBIG (-1e30f)

// ---------------- scratch ----------------
__device__ float g_sim [(size_t)B*C*Q];     // raw sim (never rewritten)
__device__ float g_rS  [B*Q];
__device__ float g_cmax[B*Q];
__device__ float g_smax[B*C];
__device__ float g_cdash[B*D];
__device__ float g_bq  [B*Q];
__device__ __nv_bfloat16 g_Qh[(size_t)B*Q*D];   // ques hi image
__device__ __nv_bfloat16 g_Ql[(size_t)B*Q*D];   // ques lo image

// ---------------- helpers ----------------
__device__ __forceinline__ unsigned smem_u32(const void* p) {
    unsigned a;
    asm("{ .reg .u64 tmp; cvta.to.shared.u64 tmp, %1; cvt.u32.u64 %0, tmp; }" : "=r"(a) : "l"(p));
    return a;
}
__device__ __forceinline__ void ldm_x4(unsigned* r, const void* p) {
    unsigned a = smem_u32(p);
    asm volatile("ldmatrix.sync.aligned.m8n8.x4.shared.b16 {%0,%1,%2,%3}, [%4];"
        : "=r"(r[0]), "=r"(r[1]), "=r"(r[2]), "=r"(r[3]) : "r"(a));
}
__device__ __forceinline__ void ldm_x4t(unsigned* r, const void* p) {
    unsigned a = smem_u32(p);
    asm volatile("ldmatrix.sync.aligned.m8n8.x4.trans.shared.b16 {%0,%1,%2,%3}, [%4];"
        : "=r"(r[0]), "=r"(r[1]), "=r"(r[2]), "=r"(r[3]) : "r"(a));
}
__device__ __forceinline__ void mma_bf16(float* d, const unsigned* a, unsigned b0, unsigned b1) {
    asm volatile("mma.sync.aligned.m16n8k16.row.col.f32.bf16.bf16.f32 "
        "{%0,%1,%2,%3}, {%4,%5,%6,%7}, {%8,%9}, {%0,%1,%2,%3};"
        : "+f"(d[0]), "+f"(d[1]), "+f"(d[2]), "+f"(d[3])
        : "r"(a[0]), "r"(a[1]), "r"(a[2]), "r"(a[3]), "r"(b0), "r"(b1));
}
__device__ __forceinline__ void split2(float x0, float x1, unsigned& h, unsigned& l) {
    __nv_bfloat16 h0 = __float2bfloat16(x0), h1 = __float2bfloat16(x1);
    float r0 = x0 - __bfloat162float(h0), r1 = x1 - __bfloat162float(h1);
    __nv_bfloat16 l0 = __float2bfloat16(r0), l1 = __float2bfloat16(r1);
    unsigned short a0 = *(unsigned short*)&h0, a1 = *(unsigned short*)&h1;
    unsigned short b0 = *(unsigned short*)&l0, b1 = *(unsigned short*)&l1;
    h = (unsigned)a0 | ((unsigned)a1 << 16);
    l = (unsigned)b0 | ((unsigned)b1 << 16);
}

#define SSTRIDE 132

// ================= K0: ques -> bf16 hi/lo images + q.w2 =================
__global__ __launch_bounds__(256) void k_convQ(const float* __restrict__ ques,
                                               const float* __restrict__ SW) {
    const int b = blockIdx.x;
    const int t = threadIdx.x;
    const int row = t >> 1, half = t & 1;
    const float* src = ques + ((size_t)(b * Q + row)) * D + half * 384;
    const float* w2 = SW + D + half * 384;
    __nv_bfloat16* dh = g_Qh + ((size_t)(b * Q + row)) * D + half * 384;
    __nv_bfloat16* dl = g_Ql + ((size_t)(b * Q + row)) * D + half * 384;
    float acc = 0.f;
    #pragma unroll 4
    for (int g = 0; g < 48; g++) {
        float4 v0 = *(const float4*)(src + g * 8);
        float4 v1 = *(const float4*)(src + g * 8 + 4);
        float4 w0 = *(const float4*)(w2 + g * 8);
        float4 w1 = *(const float4*)(w2 + g * 8 + 4);
        acc += v0.x*w0.x + v0.y*w0.y + v0.z*w0.z + v0.w*w0.w
             + v1.x*w1.x + v1.y*w1.y + v1.z*w1.z + v1.w*w1.w;
        unsigned h0, l0, h1, l1, h2, l2, h3, l3;
        split2(v0.x, v0.y, h0, l0);
        split2(v0.z, v0.w, h1, l1);
        split2(v1.x, v1.y, h2, l2);
        split2(v1.z, v1.w, h3, l3);
        *(uint4*)(dh + g * 8) = make_uint4(h0, h1, h2, h3);
        *(uint4*)(dl + g * 8) = make_uint4(l0, l1, l2, l3);
    }
    acc += __shfl_xor_sync(0xffffffffu, acc, 1);
    if (half == 0) g_bq[b * Q + row] = acc;
}

// ================= K1: sim GEMM =================
// tile 64(c) x 128(q), BK=32, 8 warps
__global__ __launch_bounds__(256, 2) void k_sim_mma(const float* __restrict__ cont,
                                                    const float* __restrict__ SW) {
    __shared__ char buf[64 * SSTRIDE * 4];
    __shared__ float sm_a[64], sm_bq[128];
    __nv_bfloat16 (*Ah)[40] = (__nv_bfloat16 (*)[40])(buf);
    __nv_bfloat16 (*Al)[40] = (__nv_bfloat16 (*)[40])(buf + 5120);
    __nv_bfloat16 (*Bh)[40] = (__nv_bfloat16 (*)[40])(buf + 10240);
    __nv_bfloat16 (*Bl)[40] = (__nv_bfloat16 (*)[40])(buf + 20480);
    float* S = (float*)buf;

    const int cb = blockIdx.x, b = blockIdx.y;
    const int t = threadIdx.x, lane = t & 31, wid = t >> 5;
    const int wm = wid & 1, wn = wid >> 1;
    const int arow = t >> 2, acol = (t & 3) * 8;

    if (t < 128) sm_bq[t] = g_bq[b * Q + t];

    const float* Ag = cont + ((size_t)(b * C + cb * 64 + arow)) * D + acol;
    const __nv_bfloat16* Qh = g_Qh + ((size_t)b * Q) * D;
    const __nv_bfloat16* Ql = g_Ql + ((size_t)b * Q) * D;
    const float* w1 = SW;
    const float* w3 = SW + 2 * D;

    float acc[2][4][4];
    #pragma unroll
    for (int i = 0; i < 2; i++)
        #pragma unroll
        for (int j = 0; j < 4; j++)
            #pragma unroll
            for (int k = 0; k < 4; k++) acc[i][j][k] = 0.f;

    float a_part = 0.f;
    float4 ra[2];
    #pragma unroll
    for (int j = 0; j < 2; j++) ra[j] = *(const float4*)(Ag + j * 4);

    for (int k0 = 0; k0 < D; k0 += 32) {
        if (k0) __syncthreads();
        #pragma unroll
        for (int j = 0; j < 2; j++) {
            int col = acol + j * 4;
            float4 w3v = *(const float4*)(w3 + k0 + col);
            float4 w1v = *(const float4*)(w1 + k0 + col);
            a_part += ra[j].x * w1v.x + ra[j].y * w1v.y + ra[j].z * w1v.z + ra[j].w * w1v.w;
            unsigned h0, l0, h1, l1;
            split2(ra[j].x * w3v.x, ra[j].y * w3v.y, h0, l0);
            split2(ra[j].z * w3v.z, ra[j].w * w3v.w, h1, l1);
            *(unsigned*)&Ah[arow][col]     = h0;  *(unsigned*)&Al[arow][col]     = l0;
            *(unsigned*)&Ah[arow][col + 2] = h1;  *(unsigned*)&Al[arow][col + 2] = l1;
        }
        // B copy: 128 rows x 32 cols bf16 hi/lo
        #pragma unroll
        for (int i = 0; i < 2; i++) {
            int idx = t + i * 256;
            int r = idx >> 2, cl = idx & 3;
            *(uint4*)&Bh[r][cl * 8] = *(const uint4*)(Qh + (size_t)r * D + k0 + cl * 8);
            *(uint4*)&Bl[r][cl * 8] = *(const uint4*)(Ql + (size_t)r * D + k0 + cl * 8);
        }
        __syncthreads();
        if (k0 + 32 < D) {
            #pragma unroll
            for (int j = 0; j < 2; j++) ra[j] = *(const float4*)(Ag + k0 + 32 + j * 4);
        }
        #pragma unroll
        for (int kk = 0; kk < 2; kk++) {
            const int kb = kk * 16;
            unsigned afh[2][4], afl[2][4];
            #pragma unroll
            for (int mt = 0; mt < 2; mt++) {
                ldm_x4(afh[mt], &Ah[wm * 32 + mt * 16 + (lane & 15)][kb + (lane >> 4) * 8]);
                ldm_x4(afl[mt], &Al[wm * 32 + mt * 16 + (lane & 15)][kb + (lane >> 4) * 8]);
            }
            #pragma unroll
            for (int ng = 0; ng < 2; ng++) {
                unsigned bfh[4], bfl[4];
                ldm_x4(bfh, &Bh[wn * 32 + ng * 16 + (lane & 15)][kb + (lane >> 4) * 8]);
                ldm_x4(bfl, &Bl[wn * 32 + ng * 16 + (lane & 15)][kb + (lane >> 4) * 8]);
                #pragma unroll
                for (int h = 0; h < 2; h++) {
                    const int nt = ng * 2 + h;
                    #pragma unroll
                    for (int mt = 0; mt < 2; mt++) {
                        mma_bf16(acc[mt][nt], afh[mt], bfh[h], bfh[2 + h]);
                        mma_bf16(acc[mt][nt], afh[mt], bfl[h], bfl[2 + h]);
                        mma_bf16(acc[mt][nt], afl[mt], bfh[h], bfh[2 + h]);
                    }
                }
            }
        }
    }

    a_part += __shfl_xor_sync(0xffffffffu, a_part, 1);
    a_part += __shfl_xor_sync(0xffffffffu, a_part, 2);
    if ((t & 3) == 0) sm_a[arow] = a_part;
    __syncthreads();

    // stage accumulators
    #pragma unroll
    for (int mt = 0; mt < 2; mt++) {
        const int r0 = wm * 32 + mt * 16 + (lane >> 2);
        #pragma unroll
        for (int nt = 0; nt < 4; nt++) {
            const int q0 = wn * 32 + nt * 8 + (lane & 3) * 2;
            *(float2*)&S[r0 * SSTRIDE + q0]       = make_float2(acc[mt][nt][0], acc[mt][nt][1]);
            *(float2*)&S[(r0 + 8) * SSTRIDE + q0] = make_float2(acc[mt][nt][2], acc[mt][nt][3]);
        }
    }
    __syncthreads();

    float4 bq4 = *(const float4*)&sm_bq[lane * 4];
    #pragma unroll
    for (int r = 0; r < 8; r++) {
        const int row = wid * 8 + r;
        float4 v = *(const float4*)&S[row * SSTRIDE + lane * 4];
        float a = sm_a[row];
        v.x += a + bq4.x; v.y += a + bq4.y; v.z += a + bq4.z; v.w += a + bq4.w;
        float m = fmaxf(fmaxf(v.x, v.y), fmaxf(v.z, v.w));
        #pragma unroll
        for (int o = 16; o; o >>= 1) m = fmaxf(m, __shfl_xor_sync(0xffffffffu, m, o));
        *(float4*)(g_sim + ((size_t)(b * C + cb * 64 + row)) * Q + lane * 4) = v;
        if (lane == 0) g_smax[b * C + cb * 64 + row] = m;
    }
}

// ================= K2: column softmax stats (read-only) =================
__global__ void k_colstats(const int* __restrict__ qmask) {
    const int b  = blockIdx.y;
    const int tx = threadIdx.x, ty = threadIdx.y;
    const int q  = blockIdx.x * 32 + tx;
    const int qm = qmask[b * Q + q];
    __shared__ float red[8][32];
    float m = -3.4e38f;
    for (int c = ty; c < C; c += 8) {
        float v = g_sim[((size_t)(b * C + c)) * Q + q];
        m = fmaxf(m, qm ? v : NEGBIG);
    }
    red[ty][tx] = m;
    __syncthreads();
    if (ty == 0) {
        #pragma unroll
        for (int k = 1; k < 8; k++) m = fmaxf(m, red[k][tx]);
        red[0][tx] = m;
    }
    __syncthreads();
    m = red[0][tx];
    __syncthreads();
    float s = 0.f;
    for (int c = ty; c < C; c += 8) {
        float v = g_sim[((size_t)(b * C + c)) * Q + q];
        s += expf((qm ? v : NEGBIG) - m);
    }
    red[ty][tx] = s;
    __syncthreads();
    if (ty == 0) {
        #pragma unroll
        for (int k = 1; k < 8; k++) s += red[k][tx];
        g_cmax[b * Q + q] = m;
        g_rS[b * Q + q] = 1.f / s;
    }
}

// ================= K3: c_dash (weights inline) =================
__global__ __launch_bounds__(256) void k_cdashW(const float* __restrict__ cont,
                                                const int* __restrict__ cmask) {
    __shared__ float red[256];
    __shared__ float w[512];
    const int b = blockIdx.y;
    const int t = threadIdx.x;
    float s0 = g_smax[b * C + t], s1 = g_smax[b * C + 256 + t];
    float ms0 = cmask[b * C + t] ? s0 : NEGBIG;
    float ms1 = cmask[b * C + 256 + t] ? s1 : NEGBIG;
    red[t] = fmaxf(ms0, ms1);
    __syncthreads();
    for (int o = 128; o; o >>= 1) {
        if (t < o) red[t] = fmaxf(red[t], red[t + o]);
        __syncthreads();
    }
    float M = red[0];
    __syncthreads();
    float e0 = expf(ms0 - M), e1 = expf(ms1 - M);
    red[t] = e0 + e1;
    __syncthreads();
    for (int o = 128; o; o >>= 1) {
        if (t < o) red[t] += red[t + o];
        __syncthreads();
    }
    float rS = 1.f / red[0];
    w[t] = e0 * rS;
    w[256 + t] = e1 * rS;
    __syncthreads();
    const int d = blockIdx.x * 256 + t;
    float acc = 0.f;
    const float* base = cont + (size_t)b * C * D + d;
    #pragma unroll 8
    for (int c = 0; c < C; c++) acc += w[c] * base[(size_t)c * D];
    g_cdash[b * D + d] = acc;
}

// ================= K4: c2q GEMM, A resident, dt loop + epilogue =================
#define C2Q_ASZ (2 * 64 * 136 * 2)              // Ah+Al = 34816
#define C2Q_SMEM (C2Q_ASZ + 64 * SSTRIDE * 4)   // + staging/B region = 68608
__global__ __launch_bounds__(256, 2) void k_c2q_mma(const float* __restrict__ cont,
                                                    const int* __restrict__ qmask,
                                                    float* __restrict__ out) {
    extern __shared__ char buf[];
    __shared__ float sm_rs[128], sm_cmax[128], sm_cd[128];
    __shared__ int sm_qm[128];
    __nv_bfloat16 (*Ah)[136] = (__nv_bfloat16 (*)[136])(buf);
    __nv_bfloat16 (*Al)[136] = (__nv_bfloat16 (*)[136])(buf + 64 * 136 * 2);
    __nv_bfloat16 (*Bh)[136] = (__nv_bfloat16 (*)[136])(buf + C2Q_ASZ);
    __nv_bfloat16 (*Bl)[136] = (__nv_bfloat16 (*)[136])(buf + C2Q_ASZ + 32 * 136 * 2);
    float* S = (float*)(buf + C2Q_ASZ);

    const int cb = blockIdx.x, b = blockIdx.y;
    const int t = threadIdx.x, lane = t & 31, wid = t >> 5;
    const int wm = wid & 1, wn = wid >> 1;

    if (t < 128) {
        sm_rs[t]   = g_rS[b * Q + t];
        sm_cmax[t] = g_cmax[b * Q + t];
        sm_qm[t]   = qmask[b * Q + t];
    }
    __syncthreads();

    // build A (dist, split) once: 64 rows (c local) x 128 cols (q)
    {
        const int row = t >> 2, qtr = t & 3;      // each quarter covers 32 q cols
        const float* sp = g_sim + ((size_t)(b * C + cb * 64 + row)) * Q + qtr * 32;
        #pragma unroll
        for (int g = 0; g < 4; g++) {
            const int col = qtr * 32 + g * 8;
            float4 v0 = *(const float4*)(sp + g * 8);
            float4 v1 = *(const float4*)(sp + g * 8 + 4);
            float raw[8] = { v0.x, v0.y, v0.z, v0.w, v1.x, v1.y, v1.z, v1.w };
            unsigned hh[4], ll[4];
            #pragma unroll
            for (int j = 0; j < 2; j++) {
                int q0 = col + j * 4;
                float x0 = (sm_qm[q0+0] ? expf(raw[j*4+0] - sm_cmax[q0+0]) : 1.f) * sm_rs[q0+0];
                float x1 = (sm_qm[q0+1] ? expf(raw[j*4+1] - sm_cmax[q0+1]) : 1.f) * sm_rs[q0+1];
                float x2 = (sm_qm[q0+2] ? expf(raw[j*4+2] - sm_cmax[q0+2]) : 1.f) * sm_rs[q0+2];
                float x3 = (sm_qm[q0+3] ? expf(raw[j*4+3] - sm_cmax[q0+3]) : 1.f) * sm_rs[q0+3];
                split2(x0, x1, hh[j*2], ll[j*2]);
                split2(x2, x3, hh[j*2+1], ll[j*2+1]);
            }
            *(uint4*)&Ah[row][col] = make_uint4(hh[0], hh[1], hh[2], hh[3]);
            *(uint4*)&Al[row][col] = make_uint4(ll[0], ll[1], ll[2], ll[3]);
        }
    }
    __syncthreads();

    const __nv_bfloat16* Qh = g_Qh + ((size_t)b * Q) * D;
    const __nv_bfloat16* Ql = g_Ql + ((size_t)b * Q) * D;

    for (int dt = 0; dt < 6; dt++) {
        if (t < 128) sm_cd[t] = g_cdash[b * D + dt * 128 + t];

        float acc[2][4][4];
        #pragma unroll
        for (int i = 0; i < 2; i++)
            #pragma unroll
            for (int j = 0; j < 4; j++)
                #pragma unroll
                for (int k = 0; k < 4; k++) acc[i][j][k] = 0.f;

        #pragma unroll
        for (int k0 = 0; k0 < Q; k0 += 32) {
            // B copy: 32 q-rows x 128 d-cols bf16 hi/lo
            #pragma unroll
            for (int i = 0; i < 2; i++) {
                int idx = t + i * 256;
                int r = idx >> 4, cl = idx & 15;
                *(uint4*)&Bh[r][cl * 8] =
                    *(const uint4*)(Qh + (size_t)(k0 + r) * D + dt * 128 + cl * 8);
                *(uint4*)&Bl[r][cl * 8] =
                    *(const uint4*)(Ql + (size_t)(k0 + r) * D + dt * 128 + cl * 8);
            }
            __syncthreads();
            #pragma unroll
            for (int kk = 0; kk < 2; kk++) {
                const int kb = k0 + kk * 16;
                unsigned afh[2][4], afl[2][4];
                #pragma unroll
                for (int mt = 0; mt < 2; mt++) {
                    ldm_x4(afh[mt], &Ah[wm * 32 + mt * 16 + (lane & 15)][kb + (lane >> 4) * 8]);
                    ldm_x4(afl[mt], &Al[wm * 32 + mt * 16 + (lane & 15)][kb + (lane >> 4) * 8]);
                }
                #pragma unroll
                for (int ng = 0; ng < 2; ng++) {
                    unsigned bfh[4], bfl[4];
                    ldm_x4t(bfh, &Bh[kk * 16 + (lane & 15)][wn * 32 + ng * 16 + (lane >> 4) * 8]);
                    ldm_x4t(bfl, &Bl[kk * 16 + (lane & 15)][wn * 32 + ng * 16 + (lane >> 4) * 8]);
                    #pragma unroll
                    for (int h = 0; h < 2; h++) {
                        const int nt = ng * 2 + h;
                        #pragma unroll
                        for (int mt = 0; mt < 2; mt++) {
                            mma_bf16(acc[mt][nt], afh[mt], bfh[2 * h], bfh[2 * h + 1]);
                            mma_bf16(acc[mt][nt], afh[mt], bfl[2 * h], bfl[2 * h + 1]);
                            mma_bf16(acc[mt][nt], afl[mt], bfh[2 * h], bfh[2 * h + 1]);
                        }
                    }
                }
            }
            __syncthreads();   // B dead before next chunk / staging overwrite
        }

        // stage accumulators into S (overlays B region)
        #pragma unroll
        for (int mt = 0; mt < 2; mt++) {
            const int r0 = wm * 32 + mt * 16 + (lane >> 2);
            #pragma unroll
            for (int nt = 0; nt < 4; nt++) {
                const int d0 = wn * 32 + nt * 8 + (lane & 3) * 2;
                *(float2*)&S[r0 * SSTRIDE + d0]       = make_float2(acc[mt][nt][0], acc[mt][nt][1]);
                *(float2*)&S[(r0 + 8) * SSTRIDE + d0] = make_float2(acc[mt][nt][2], acc[mt][nt][3]);
            }
        }
        __syncthreads();

        float4 cd = *(const float4*)&sm_cd[lane * 4];
        #pragma unroll
        for (int r = 0; r < 8; r++) {
            const int row = wid * 8 + r;
            const int c = cb * 64 + row;
            float4 cq = *(const float4*)&S[row * SSTRIDE + lane * 4];
            float4 ct = *(const float4*)(cont + ((size_t)(b * C + c)) * D + dt * 128 + lane * 4);
            float4 m1 = make_float4(ct.x * cq.x, ct.y * cq.y, ct.z * cq.z, ct.w * cq.w);
            float4 m2 = make_float4(ct.x * cd.x, ct.y * cd.y, ct.z * cd.z, ct.w * cd.w);
            float* ob = out + ((size_t)(b * C + c)) * OD + dt * 128 + lane * 4;
            *(float4*)(ob)         = ct;
            *(float4*)(ob + D)     = cq;
            *(float4*)(ob + 2 * D) = m1;
            *(float4*)(ob + 3 * D) = m2;
        }
        __syncthreads();   // S dead before next dt's B copy
    }
}

// ---------------- launch ----------------
extern "C" void kernel_launch(void* const* d_in, const int* in_sizes, int n_in,
                              void* d_out, int out_size) {
    const float* cont  = (const float*)d_in[0];
    const int*   cmask = (const int*)d_in[1];
    const float* ques  = (const float*)d_in[2];
    const int*   qmask = (const int*)d_in[3];
    const float* SW    = (const float*)d_in[4];
    float* out = (float*)d_out;
    (void)in_sizes; (void)n_in; (void)out_size;

    cudaFuncSetAttribute(k_c2q_mma, cudaFuncAttributeMaxDynamicSharedMemorySize, C2Q_SMEM);

    {                           k_convQ<<<B, 256>>>(ques, SW); }
    {   dim3 g(C / 64, B);      k_sim_mma<<<g, 256>>>(cont, SW); }
    {   dim3 g(Q / 32, B);      dim3 th(32, 8); k_colstats<<<g, th>>>(qmask); }
    {   dim3 g(D / 256, B);     k_cdashW<<<g, 256>>>(cont, cmask); }
    {   dim3 g(C / 64, B);      k_c2q_mma<<<g, 256, C2Q_SMEM>>>(cont, qmask, out); }
}

// round 9
// speedup vs baseline: 1.0763x; 1.0763x over previous
#include <cuda_runtime.h>
#include <cuda_bf16.h>
#include <math.h>
#include <stdint.h>

#define B 32
#define C 512
#define Q 128
#define D 768
#define OD (4*D)
#define NEGBIG (-1e30f)

// ---------------- scratch ----------------
__device__ float g_sim [(size_t)B*C*Q];     // raw sim, then e in place
__device__ float g_rS  [B*Q];
__device__ float g_smax[B*C];
__device__ float g_cdw [B*C];
__device__ float g_cdash[B*D];
__device__ float g_bq  [B*Q];
__device__ __nv_bfloat16 g_Qh[(size_t)B*Q*D];
__device__ __nv_bfloat16 g_Ql[(size_t)B*Q*D];

// ---------------- helpers ----------------
__device__ __forceinline__ unsigned smem_u32(const void* p) {
    unsigned a;
    asm("{ .reg .u64 tmp; cvta.to.shared.u64 tmp, %1; cvt.u32.u64 %0, tmp; }" : "=r"(a) : "l"(p));
    return a;
}
__device__ __forceinline__ void ldm_x4(unsigned* r, const void* p) {
    unsigned a = smem_u32(p);
    asm volatile("ldmatrix.sync.aligned.m8n8.x4.shared.b16 {%0,%1,%2,%3}, [%4];"
        : "=r"(r[0]), "=r"(r[1]), "=r"(r[2]), "=r"(r[3]) : "r"(a));
}
__device__ __forceinline__ void ldm_x4t(unsigned* r, const void* p) {
    unsigned a = smem_u32(p);
    asm volatile("ldmatrix.sync.aligned.m8n8.x4.trans.shared.b16 {%0,%1,%2,%3}, [%4];"
        : "=r"(r[0]), "=r"(r[1]), "=r"(r[2]), "=r"(r[3]) : "r"(a));
}
__device__ __forceinline__ void mma_bf16(float* d, const unsigned* a, unsigned b0, unsigned b1) {
    asm volatile("mma.sync.aligned.m16n8k16.row.col.f32.bf16.bf16.f32 "
        "{%0,%1,%2,%3}, {%4,%5,%6,%7}, {%8,%9}, {%0,%1,%2,%3};"
        : "+f"(d[0]), "+f"(d[1]), "+f"(d[2]), "+f"(d[3])
        : "r"(a[0]), "r"(a[1]), "r"(a[2]), "r"(a[3]), "r"(b0), "r"(b1));
}
__device__ __forceinline__ void split2(float x0, float x1, unsigned& h, unsigned& l) {
    __nv_bfloat16 h0 = __float2bfloat16(x0), h1 = __float2bfloat16(x1);
    float r0 = x0 - __bfloat162float(h0), r1 = x1 - __bfloat162float(h1);
    __nv_bfloat16 l0 = __float2bfloat16(r0), l1 = __float2bfloat16(r1);
    unsigned short a0 = *(unsigned short*)&h0, a1 = *(unsigned short*)&h1;
    unsigned short b0 = *(unsigned short*)&l0, b1 = *(unsigned short*)&l1;
    h = (unsigned)a0 | ((unsigned)a1 << 16);
    l = (unsigned)b0 | ((unsigned)b1 << 16);
}

#define SSTRIDE 132

// ================= K0: ques -> bf16 hi/lo images + q.w2 =================
__global__ __launch_bounds__(256) void k_convQ(const float* __restrict__ ques,
                                               const float* __restrict__ SW) {
    const int b = blockIdx.x;
    const int t = threadIdx.x;
    const int row = t >> 1, half = t & 1;
    const float* src = ques + ((size_t)(b * Q + row)) * D + half * 384;
    const float* w2 = SW + D + half * 384;
    __nv_bfloat16* dh = g_Qh + ((size_t)(b * Q + row)) * D + half * 384;
    __nv_bfloat16* dl = g_Ql + ((size_t)(b * Q + row)) * D + half * 384;
    float acc = 0.f;
    #pragma unroll 4
    for (int g = 0; g < 48; g++) {
        float4 v0 = *(const float4*)(src + g * 8);
        float4 v1 = *(const float4*)(src + g * 8 + 4);
        float4 w0 = *(const float4*)(w2 + g * 8);
        float4 w1 = *(const float4*)(w2 + g * 8 + 4);
        acc += v0.x*w0.x + v0.y*w0.y + v0.z*w0.z + v0.w*w0.w
             + v1.x*w1.x + v1.y*w1.y + v1.z*w1.z + v1.w*w1.w;
        unsigned h0, l0, h1, l1, h2, l2, h3, l3;
        split2(v0.x, v0.y, h0, l0);
        split2(v0.z, v0.w, h1, l1);
        split2(v1.x, v1.y, h2, l2);
        split2(v1.z, v1.w, h3, l3);
        *(uint4*)(dh + g * 8) = make_uint4(h0, h1, h2, h3);
        *(uint4*)(dl + g * 8) = make_uint4(l0, l1, l2, l3);
    }
    acc += __shfl_xor_sync(0xffffffffu, acc, 1);
    if (half == 0) g_bq[b * Q + row] = acc;
}

// ================= K1: sim GEMM =================
__global__ __launch_bounds__(256, 2) void k_sim_mma(const float* __restrict__ cont,
                                                    const float* __restrict__ SW) {
    __shared__ char buf[64 * SSTRIDE * 4];
    __shared__ float sm_a[64], sm_bq[128];
    __nv_bfloat16 (*Ah)[40] = (__nv_bfloat16 (*)[40])(buf);
    __nv_bfloat16 (*Al)[40] = (__nv_bfloat16 (*)[40])(buf + 5120);
    __nv_bfloat16 (*Bh)[40] = (__nv_bfloat16 (*)[40])(buf + 10240);
    __nv_bfloat16 (*Bl)[40] = (__nv_bfloat16 (*)[40])(buf + 20480);
    float* S = (float*)buf;

    const int cb = blockIdx.x, b = blockIdx.y;
    const int t = threadIdx.x, lane = t & 31, wid = t >> 5;
    const int wm = wid & 1, wn = wid >> 1;
    const int arow = t >> 2, acol = (t & 3) * 8;

    if (t < 128) sm_bq[t] = g_bq[b * Q + t];

    const float* Ag = cont + ((size_t)(b * C + cb * 64 + arow)) * D + acol;
    const __nv_bfloat16* Qh = g_Qh + ((size_t)b * Q) * D;
    const __nv_bfloat16* Ql = g_Ql + ((size_t)b * Q) * D;
    const float* w1 = SW;
    const float* w3 = SW + 2 * D;

    float acc[2][4][4];
    #pragma unroll
    for (int i = 0; i < 2; i++)
        #pragma unroll
        for (int j = 0; j < 4; j++)
            #pragma unroll
            for (int k = 0; k < 4; k++) acc[i][j][k] = 0.f;

    float a_part = 0.f;
    float4 ra[2];
    #pragma unroll
    for (int j = 0; j < 2; j++) ra[j] = *(const float4*)(Ag + j * 4);

    for (int k0 = 0; k0 < D; k0 += 32) {
        if (k0) __syncthreads();
        #pragma unroll
        for (int j = 0; j < 2; j++) {
            int col = acol + j * 4;
            float4 w3v = *(const float4*)(w3 + k0 + col);
            float4 w1v = *(const float4*)(w1 + k0 + col);
            a_part += ra[j].x * w1v.x + ra[j].y * w1v.y + ra[j].z * w1v.z + ra[j].w * w1v.w;
            unsigned h0, l0, h1, l1;
            split2(ra[j].x * w3v.x, ra[j].y * w3v.y, h0, l0);
            split2(ra[j].z * w3v.z, ra[j].w * w3v.w, h1, l1);
            *(unsigned*)&Ah[arow][col]     = h0;  *(unsigned*)&Al[arow][col]     = l0;
            *(unsigned*)&Ah[arow][col + 2] = h1;  *(unsigned*)&Al[arow][col + 2] = l1;
        }
        #pragma unroll
        for (int i = 0; i < 2; i++) {
            int idx = t + i * 256;
            int r = idx >> 2, cl = idx & 3;
            *(uint4*)&Bh[r][cl * 8] = *(const uint4*)(Qh + (size_t)r * D + k0 + cl * 8);
            *(uint4*)&Bl[r][cl * 8] = *(const uint4*)(Ql + (size_t)r * D + k0 + cl * 8);
        }
        __syncthreads();
        if (k0 + 32 < D) {
            #pragma unroll
            for (int j = 0; j < 2; j++) ra[j] = *(const float4*)(Ag + k0 + 32 + j * 4);
        }
        #pragma unroll
        for (int kk = 0; kk < 2; kk++) {
            const int kb = kk * 16;
            unsigned afh[2][4], afl[2][4];
            #pragma unroll
            for (int mt = 0; mt < 2; mt++) {
                ldm_x4(afh[mt], &Ah[wm * 32 + mt * 16 + (lane & 15)][kb + (lane >> 4) * 8]);
                ldm_x4(afl[mt], &Al[wm * 32 + mt * 16 + (lane & 15)][kb + (lane >> 4) * 8]);
            }
            #pragma unroll
            for (int ng = 0; ng < 2; ng++) {
                unsigned bfh[4], bfl[4];
                ldm_x4(bfh, &Bh[wn * 32 + ng * 16 + (lane & 15)][kb + (lane >> 4) * 8]);
                ldm_x4(bfl, &Bl[wn * 32 + ng * 16 + (lane & 15)][kb + (lane >> 4) * 8]);
                #pragma unroll
                for (int h = 0; h < 2; h++) {
                    const int nt = ng * 2 + h;
                    #pragma unroll
                    for (int mt = 0; mt < 2; mt++) {
                        mma_bf16(acc[mt][nt], afh[mt], bfh[h], bfh[2 + h]);
                        mma_bf16(acc[mt][nt], afh[mt], bfl[h], bfl[2 + h]);
                        mma_bf16(acc[mt][nt], afl[mt], bfh[h], bfh[2 + h]);
                    }
                }
            }
        }
    }

    a_part += __shfl_xor_sync(0xffffffffu, a_part, 1);
    a_part += __shfl_xor_sync(0xffffffffu, a_part, 2);
    if ((t & 3) == 0) sm_a[arow] = a_part;
    __syncthreads();

    #pragma unroll
    for (int mt = 0; mt < 2; mt++) {
        const int r0 = wm * 32 + mt * 16 + (lane >> 2);
        #pragma unroll
        for (int nt = 0; nt < 4; nt++) {
            const int q0 = wn * 32 + nt * 8 + (lane & 3) * 2;
            *(float2*)&S[r0 * SSTRIDE + q0]       = make_float2(acc[mt][nt][0], acc[mt][nt][1]);
            *(float2*)&S[(r0 + 8) * SSTRIDE + q0] = make_float2(acc[mt][nt][2], acc[mt][nt][3]);
        }
    }
    __syncthreads();

    float4 bq4 = *(const float4*)&sm_bq[lane * 4];
    #pragma unroll
    for (int r = 0; r < 8; r++) {
        const int row = wid * 8 + r;
        float4 v = *(const float4*)&S[row * SSTRIDE + lane * 4];
        float a = sm_a[row];
        v.x += a + bq4.x; v.y += a + bq4.y; v.z += a + bq4.z; v.w += a + bq4.w;
        float m = fmaxf(fmaxf(v.x, v.y), fmaxf(v.z, v.w));
        #pragma unroll
        for (int o = 16; o; o >>= 1) m = fmaxf(m, __shfl_xor_sync(0xffffffffu, m, o));
        *(float4*)(g_sim + ((size_t)(b * C + cb * 64 + row)) * Q + lane * 4) = v;
        if (lane == 0) g_smax[b * C + cb * 64 + row] = m;
    }
}

// ================= K2: column softmax, write e in place =================
__global__ void k_colstats(const int* __restrict__ qmask) {
    const int b  = blockIdx.y;
    const int tx = threadIdx.x, ty = threadIdx.y;
    const int q  = blockIdx.x * 32 + tx;
    const int qm = qmask[b * Q + q];
    __shared__ float red[8][32];
    float m = -3.4e38f;
    for (int c = ty; c < C; c += 8) {
        float v = g_sim[((size_t)(b * C + c)) * Q + q];
        m = fmaxf(m, qm ? v : NEGBIG);
    }
    red[ty][tx] = m;
    __syncthreads();
    if (ty == 0) {
        #pragma unroll
        for (int k = 1; k < 8; k++) m = fmaxf(m, red[k][tx]);
        red[0][tx] = m;
    }
    __syncthreads();
    m = red[0][tx];
    __syncthreads();
    float s = 0.f;
    for (int c = ty; c < C; c += 8) {
        size_t idx = ((size_t)(b * C + c)) * Q + q;
        float v = g_sim[idx];
        float e = expf((qm ? v : NEGBIG) - m);
        g_sim[idx] = e;
        s += e;
    }
    red[ty][tx] = s;
    __syncthreads();
    if (ty == 0) {
        #pragma unroll
        for (int k = 1; k < 8; k++) s += red[k][tx];
        g_rS[b * Q + q] = 1.f / s;
    }
}

// ================= K3: c_dash weights =================
__global__ __launch_bounds__(512) void k_cweights(const int* __restrict__ cmask) {
    const int b = blockIdx.x;
    const int t = threadIdx.x;
    __shared__ float red[512];
    float ms = cmask[b * C + t] ? g_smax[b * C + t] : NEGBIG;
    red[t] = ms;
    __syncthreads();
    for (int o = 256; o; o >>= 1) {
        if (t < o) red[t] = fmaxf(red[t], red[t + o]);
        __syncthreads();
    }
    float M = red[0];
    __syncthreads();
    float e = expf(ms - M);
    red[t] = e;
    __syncthreads();
    for (int o = 256; o; o >>= 1) {
        if (t < o) red[t] += red[t + o];
        __syncthreads();
    }
    g_cdw[b * C + t] = e / red[0];
}

// ================= K4: c_dash (parallel over 64-d chunks x 4 c-strips) =================
__global__ __launch_bounds__(256) void k_cdash(const float* __restrict__ cont) {
    const int b = blockIdx.y, d0 = blockIdx.x * 64;
    const int t = threadIdx.x;
    const int dl = t & 63, cs = t >> 6;   // 4 strips of 128 c
    __shared__ float w[512];
    __shared__ float red[4][64];
    for (int c = t; c < 512; c += 256) w[c] = g_cdw[b * C + c];
    __syncthreads();
    float acc = 0.f;
    const float* base = cont + ((size_t)(b * C + cs * 128)) * D + d0 + dl;
    const float* wp = &w[cs * 128];
    #pragma unroll 4
    for (int c = 0; c < 128; c++) acc += wp[c] * base[(size_t)c * D];
    red[cs][dl] = acc;
    __syncthreads();
    if (t < 64)
        g_cdash[b * D + d0 + t] = (red[0][t] + red[1][t]) + (red[2][t] + red[3][t]);
}

// ================= K5: c2q GEMM, A resident, 2 dt per CTA =================
#define C2Q_ASZ (2 * 64 * 136 * 2)              // Ah+Al = 34816
#define C2Q_SMEM (C2Q_ASZ + 64 * SSTRIDE * 4)   // 68608
__global__ __launch_bounds__(256, 2) void k_c2q_mma(const float* __restrict__ cont,
                                                    float* __restrict__ out) {
    extern __shared__ char buf[];
    __shared__ float sm_rs[128], sm_cd[128];
    __nv_bfloat16 (*Ah)[136] = (__nv_bfloat16 (*)[136])(buf);
    __nv_bfloat16 (*Al)[136] = (__nv_bfloat16 (*)[136])(buf + 64 * 136 * 2);
    __nv_bfloat16 (*Bh)[136] = (__nv_bfloat16 (*)[136])(buf + C2Q_ASZ);
    __nv_bfloat16 (*Bl)[136] = (__nv_bfloat16 (*)[136])(buf + C2Q_ASZ + 32 * 136 * 2);
    float* S = (float*)(buf + C2Q_ASZ);

    const int cb = blockIdx.x, dtg = blockIdx.y, b = blockIdx.z;
    const int t = threadIdx.x, lane = t & 31, wid = t >> 5;
    const int wm = wid & 1, wn = wid >> 1;

    if (t < 128) sm_rs[t] = g_rS[b * Q + t];
    __syncthreads();

    // build A (dist = e * rS, split) once: 64 rows (c) x 128 cols (q)
    {
        const int row = t >> 2, qtr = t & 3;
        const float* sp = g_sim + ((size_t)(b * C + cb * 64 + row)) * Q + qtr * 32;
        #pragma unroll
        for (int g = 0; g < 4; g++) {
            const int col = qtr * 32 + g * 8;
            float4 v0 = *(const float4*)(sp + g * 8);
            float4 v1 = *(const float4*)(sp + g * 8 + 4);
            float raw[8] = { v0.x, v0.y, v0.z, v0.w, v1.x, v1.y, v1.z, v1.w };
            unsigned hh[4], ll[4];
            #pragma unroll
            for (int j = 0; j < 2; j++) {
                int q0 = col + j * 4;
                float x0 = raw[j*4+0] * sm_rs[q0+0];
                float x1 = raw[j*4+1] * sm_rs[q0+1];
                float x2 = raw[j*4+2] * sm_rs[q0+2];
                float x3 = raw[j*4+3] * sm_rs[q0+3];
                split2(x0, x1, hh[j*2], ll[j*2]);
                split2(x2, x3, hh[j*2+1], ll[j*2+1]);
            }
            *(uint4*)&Ah[row][col] = make_uint4(hh[0], hh[1], hh[2], hh[3]);
            *(uint4*)&Al[row][col] = make_uint4(ll[0], ll[1], ll[2], ll[3]);
        }
    }
    __syncthreads();

    const __nv_bfloat16* Qh = g_Qh + ((size_t)b * Q) * D;
    const __nv_bfloat16* Ql = g_Ql + ((size_t)b * Q) * D;

    for (int dd = 0; dd < 2; dd++) {
        const int dt = dtg * 2 + dd;
        if (t < 128) sm_cd[t] = g_cdash[b * D + dt * 128 + t];

        float acc[2][4][4];
        #pragma unroll
        for (int i = 0; i < 2; i++)
            #pragma unroll
            for (int j = 0; j < 4; j++)
                #pragma unroll
                for (int k = 0; k < 4; k++) acc[i][j][k] = 0.f;

        #pragma unroll
        for (int k0 = 0; k0 < Q; k0 += 32) {
            #pragma unroll
            for (int i = 0; i < 2; i++) {
                int idx = t + i * 256;
                int r = idx >> 4, cl = idx & 15;
                *(uint4*)&Bh[r][cl * 8] =
                    *(const uint4*)(Qh + (size_t)(k0 + r) * D + dt * 128 + cl * 8);
                *(uint4*)&Bl[r][cl * 8] =
                    *(const uint4*)(Ql + (size_t)(k0 + r) * D + dt * 128 + cl * 8);
            }
            __syncthreads();
            #pragma unroll
            for (int kk = 0; kk < 2; kk++) {
                const int kb = k0 + kk * 16;
                unsigned afh[2][4], afl[2][4];
                #pragma unroll
                for (int mt = 0; mt < 2; mt++) {
                    ldm_x4(afh[mt], &Ah[wm * 32 + mt * 16 + (lane & 15)][kb + (lane >> 4) * 8]);
                    ldm_x4(afl[mt], &Al[wm * 32 + mt * 16 + (lane & 15)][kb + (lane >> 4) * 8]);
                }
                #pragma unroll
                for (int ng = 0; ng < 2; ng++) {
                    unsigned bfh[4], bfl[4];
                    ldm_x4t(bfh, &Bh[kk * 16 + (lane & 15)][wn * 32 + ng * 16 + (lane >> 4) * 8]);
                    ldm_x4t(bfl, &Bl[kk * 16 + (lane & 15)][wn * 32 + ng * 16 + (lane >> 4) * 8]);
                    #pragma unroll
                    for (int h = 0; h < 2; h++) {
                        const int nt = ng * 2 + h;
                        #pragma unroll
                        for (int mt = 0; mt < 2; mt++) {
                            mma_bf16(acc[mt][nt], afh[mt], bfh[2 * h], bfh[2 * h + 1]);
                            mma_bf16(acc[mt][nt], afh[mt], bfl[2 * h], bfl[2 * h + 1]);
                            mma_bf16(acc[mt][nt], afl[mt], bfh[2 * h], bfh[2 * h + 1]);
                        }
                    }
                }
            }
            __syncthreads();
        }

        #pragma unroll
        for (int mt = 0; mt < 2; mt++) {
            const int r0 = wm * 32 + mt * 16 + (lane >> 2);
            #pragma unroll
            for (int nt = 0; nt < 4; nt++) {
                const int d0 = wn * 32 + nt * 8 + (lane & 3) * 2;
                *(float2*)&S[r0 * SSTRIDE + d0]       = make_float2(acc[mt][nt][0], acc[mt][nt][1]);
                *(float2*)&S[(r0 + 8) * SSTRIDE + d0] = make_float2(acc[mt][nt][2], acc[mt][nt][3]);
            }
        }
        __syncthreads();

        float4 cd = *(const float4*)&sm_cd[lane * 4];
        #pragma unroll
        for (int r = 0; r < 8; r++) {
            const int row = wid * 8 + r;
            const int c = cb * 64 + row;
            float4 cq = *(const float4*)&S[row * SSTRIDE + lane * 4];
            float4 ct = *(const float4*)(cont + ((size_t)(b * C + c)) * D + dt * 128 + lane * 4);
            float4 m1 = make_float4(ct.x * cq.x, ct.y * cq.y, ct.z * cq.z, ct.w * cq.w);
            float4 m2 = make_float4(ct.x * cd.x, ct.y * cd.y, ct.z * cd.z, ct.w * cd.w);
            float* ob = out + ((size_t)(b * C + c)) * OD + dt * 128 + lane * 4;
            *(float4*)(ob)         = ct;
            *(float4*)(ob + D)     = cq;
            *(float4*)(ob + 2 * D) = m1;
            *(float4*)(ob + 3 * D) = m2;
        }
        __syncthreads();
    }
}

// ---------------- launch ----------------
extern "C" void kernel_launch(void* const* d_in, const int* in_sizes, int n_in,
                              void* d_out, int out_size) {
    const float* cont  = (const float*)d_in[0];
    const int*   cmask = (const int*)d_in[1];
    const float* ques  = (const float*)d_in[2];
    const int*   qmask = (const int*)d_in[3];
    const float* SW    = (const float*)d_in[4];
    float* out = (float*)d_out;
    (void)in_sizes; (void)n_in; (void)out_size;

    cudaFuncSetAttribute(k_c2q_mma, cudaFuncAttributeMaxDynamicSharedMemorySize, C2Q_SMEM);

    {                           k_convQ<<<B, 256>>>(ques, SW); }
    {   dim3 g(C / 64, B);      k_sim_mma<<<g, 256>>>(cont, SW); }
    {   dim3 g(Q / 32, B);      dim3 th(32, 8); k_colstats<<<g, th>>>(qmask); }
    {                           k_cweights<<<B, 512>>>(cmask); }
    {   dim3 g(D / 64, B);      k_cdash<<<g, 256>>>(cont); }
    {   dim3 g(C / 64, 3, B);   k_c2q_mma<<<g, 256, C2Q_SMEM>>>(cont, out); }
}

// round 10
// speedup vs baseline: 1.0979x; 1.0200x over previous
#include <cuda_runtime.h>
#include <cuda_bf16.h>
#include <math.h>
#include <stdint.h>

#define B 32
#define C 512
#define Q 128
#define D 768
#define OD (4*D)
#define NEGBIG (-1e30f)

// ---------------- scratch ----------------
__device__ float g_sim [(size_t)B*C*Q];     // raw sim
__device__ float g_smax[B*C];
__device__ float g_cdw [B*C];
__device__ float g_cdash[B*D];
__device__ float g_bq  [B*Q];
__device__ __nv_bfloat16 g_Qh[(size_t)B*Q*D];   // ques hi/lo images
__device__ __nv_bfloat16 g_Ql[(size_t)B*Q*D];
__device__ __nv_bfloat16 g_Dh[(size_t)B*C*Q];   // dist hi/lo images
__device__ __nv_bfloat16 g_Dl[(size_t)B*C*Q];

// ---------------- helpers ----------------
__device__ __forceinline__ unsigned smem_u32(const void* p) {
    unsigned a;
    asm("{ .reg .u64 tmp; cvta.to.shared.u64 tmp, %1; cvt.u32.u64 %0, tmp; }" : "=r"(a) : "l"(p));
    return a;
}
__device__ __forceinline__ void ldm_x4(unsigned* r, const void* p) {
    unsigned a = smem_u32(p);
    asm volatile("ldmatrix.sync.aligned.m8n8.x4.shared.b16 {%0,%1,%2,%3}, [%4];"
        : "=r"(r[0]), "=r"(r[1]), "=r"(r[2]), "=r"(r[3]) : "r"(a));
}
__device__ __forceinline__ void ldm_x4t(unsigned* r, const void* p) {
    unsigned a = smem_u32(p);
    asm volatile("ldmatrix.sync.aligned.m8n8.x4.trans.shared.b16 {%0,%1,%2,%3}, [%4];"
        : "=r"(r[0]), "=r"(r[1]), "=r"(r[2]), "=r"(r[3]) : "r"(a));
}
__device__ __forceinline__ void mma_bf16(float* d, const unsigned* a, unsigned b0, unsigned b1) {
    asm volatile("mma.sync.aligned.m16n8k16.row.col.f32.bf16.bf16.f32 "
        "{%0,%1,%2,%3}, {%4,%5,%6,%7}, {%8,%9}, {%0,%1,%2,%3};"
        : "+f"(d[0]), "+f"(d[1]), "+f"(d[2]), "+f"(d[3])
        : "r"(a[0]), "r"(a[1]), "r"(a[2]), "r"(a[3]), "r"(b0), "r"(b1));
}
__device__ __forceinline__ void split2(float x0, float x1, unsigned& h, unsigned& l) {
    __nv_bfloat16 h0 = __float2bfloat16(x0), h1 = __float2bfloat16(x1);
    float r0 = x0 - __bfloat162float(h0), r1 = x1 - __bfloat162float(h1);
    __nv_bfloat16 l0 = __float2bfloat16(r0), l1 = __float2bfloat16(r1);
    unsigned short a0 = *(unsigned short*)&h0, a1 = *(unsigned short*)&h1;
    unsigned short b0 = *(unsigned short*)&l0, b1 = *(unsigned short*)&l1;
    h = (unsigned)a0 | ((unsigned)a1 << 16);
    l = (unsigned)b0 | ((unsigned)b1 << 16);
}

#define SSTRIDE 132

// ================= K0: ques -> bf16 hi/lo images + q.w2 =================
__global__ __launch_bounds__(256) void k_convQ(const float* __restrict__ ques,
                                               const float* __restrict__ SW) {
    const int b = blockIdx.x;
    const int t = threadIdx.x;
    const int row = t >> 1, half = t & 1;
    const float* src = ques + ((size_t)(b * Q + row)) * D + half * 384;
    const float* w2 = SW + D + half * 384;
    __nv_bfloat16* dh = g_Qh + ((size_t)(b * Q + row)) * D + half * 384;
    __nv_bfloat16* dl = g_Ql + ((size_t)(b * Q + row)) * D + half * 384;
    float acc = 0.f;
    #pragma unroll 4
    for (int g = 0; g < 48; g++) {
        float4 v0 = *(const float4*)(src + g * 8);
        float4 v1 = *(const float4*)(src + g * 8 + 4);
        float4 w0 = *(const float4*)(w2 + g * 8);
        float4 w1 = *(const float4*)(w2 + g * 8 + 4);
        acc += v0.x*w0.x + v0.y*w0.y + v0.z*w0.z + v0.w*w0.w
             + v1.x*w1.x + v1.y*w1.y + v1.z*w1.z + v1.w*w1.w;
        unsigned h0, l0, h1, l1, h2, l2, h3, l3;
        split2(v0.x, v0.y, h0, l0);
        split2(v0.z, v0.w, h1, l1);
        split2(v1.x, v1.y, h2, l2);
        split2(v1.z, v1.w, h3, l3);
        *(uint4*)(dh + g * 8) = make_uint4(h0, h1, h2, h3);
        *(uint4*)(dl + g * 8) = make_uint4(l0, l1, l2, l3);
    }
    acc += __shfl_xor_sync(0xffffffffu, acc, 1);
    if (half == 0) g_bq[b * Q + row] = acc;
}

// ================= K1: sim GEMM =================
__global__ __launch_bounds__(256, 2) void k_sim_mma(const float* __restrict__ cont,
                                                    const float* __restrict__ SW) {
    __shared__ char buf[64 * SSTRIDE * 4];
    __shared__ float sm_a[64], sm_bq[128];
    __nv_bfloat16 (*Ah)[40] = (__nv_bfloat16 (*)[40])(buf);
    __nv_bfloat16 (*Al)[40] = (__nv_bfloat16 (*)[40])(buf + 5120);
    __nv_bfloat16 (*Bh)[40] = (__nv_bfloat16 (*)[40])(buf + 10240);
    __nv_bfloat16 (*Bl)[40] = (__nv_bfloat16 (*)[40])(buf + 20480);
    float* S = (float*)buf;

    const int cb = blockIdx.x, b = blockIdx.y;
    const int t = threadIdx.x, lane = t & 31, wid = t >> 5;
    const int wm = wid & 1, wn = wid >> 1;
    const int arow = t >> 2, acol = (t & 3) * 8;

    if (t < 128) sm_bq[t] = g_bq[b * Q + t];

    const float* Ag = cont + ((size_t)(b * C + cb * 64 + arow)) * D + acol;
    const __nv_bfloat16* Qh = g_Qh + ((size_t)b * Q) * D;
    const __nv_bfloat16* Ql = g_Ql + ((size_t)b * Q) * D;
    const float* w1 = SW;
    const float* w3 = SW + 2 * D;

    float acc[2][4][4];
    #pragma unroll
    for (int i = 0; i < 2; i++)
        #pragma unroll
        for (int j = 0; j < 4; j++)
            #pragma unroll
            for (int k = 0; k < 4; k++) acc[i][j][k] = 0.f;

    float a_part = 0.f;
    float4 ra[2];
    #pragma unroll
    for (int j = 0; j < 2; j++) ra[j] = *(const float4*)(Ag + j * 4);

    for (int k0 = 0; k0 < D; k0 += 32) {
        if (k0) __syncthreads();
        #pragma unroll
        for (int j = 0; j < 2; j++) {
            int col = acol + j * 4;
            float4 w3v = *(const float4*)(w3 + k0 + col);
            float4 w1v = *(const float4*)(w1 + k0 + col);
            a_part += ra[j].x * w1v.x + ra[j].y * w1v.y + ra[j].z * w1v.z + ra[j].w * w1v.w;
            unsigned h0, l0, h1, l1;
            split2(ra[j].x * w3v.x, ra[j].y * w3v.y, h0, l0);
            split2(ra[j].z * w3v.z, ra[j].w * w3v.w, h1, l1);
            *(unsigned*)&Ah[arow][col]     = h0;  *(unsigned*)&Al[arow][col]     = l0;
            *(unsigned*)&Ah[arow][col + 2] = h1;  *(unsigned*)&Al[arow][col + 2] = l1;
        }
        #pragma unroll
        for (int i = 0; i < 2; i++) {
            int idx = t + i * 256;
            int r = idx >> 2, cl = idx & 3;
            *(uint4*)&Bh[r][cl * 8] = *(const uint4*)(Qh + (size_t)r * D + k0 + cl * 8);
            *(uint4*)&Bl[r][cl * 8] = *(const uint4*)(Ql + (size_t)r * D + k0 + cl * 8);
        }
        __syncthreads();
        if (k0 + 32 < D) {
            #pragma unroll
            for (int j = 0; j < 2; j++) ra[j] = *(const float4*)(Ag + k0 + 32 + j * 4);
        }
        #pragma unroll
        for (int kk = 0; kk < 2; kk++) {
            const int kb = kk * 16;
            unsigned afh[2][4], afl[2][4];
            #pragma unroll
            for (int mt = 0; mt < 2; mt++) {
                ldm_x4(afh[mt], &Ah[wm * 32 + mt * 16 + (lane & 15)][kb + (lane >> 4) * 8]);
                ldm_x4(afl[mt], &Al[wm * 32 + mt * 16 + (lane & 15)][kb + (lane >> 4) * 8]);
            }
            #pragma unroll
            for (int ng = 0; ng < 2; ng++) {
                unsigned bfh[4], bfl[4];
                ldm_x4(bfh, &Bh[wn * 32 + ng * 16 + (lane & 15)][kb + (lane >> 4) * 8]);
                ldm_x4(bfl, &Bl[wn * 32 + ng * 16 + (lane & 15)][kb + (lane >> 4) * 8]);
                #pragma unroll
                for (int h = 0; h < 2; h++) {
                    const int nt = ng * 2 + h;
                    #pragma unroll
                    for (int mt = 0; mt < 2; mt++) {
                        mma_bf16(acc[mt][nt], afh[mt], bfh[h], bfh[2 + h]);
                        mma_bf16(acc[mt][nt], afh[mt], bfl[h], bfl[2 + h]);
                        mma_bf16(acc[mt][nt], afl[mt], bfh[h], bfh[2 + h]);
                    }
                }
            }
        }
    }

    a_part += __shfl_xor_sync(0xffffffffu, a_part, 1);
    a_part += __shfl_xor_sync(0xffffffffu, a_part, 2);
    if ((t & 3) == 0) sm_a[arow] = a_part;
    __syncthreads();

    #pragma unroll
    for (int mt = 0; mt < 2; mt++) {
        const int r0 = wm * 32 + mt * 16 + (lane >> 2);
        #pragma unroll
        for (int nt = 0; nt < 4; nt++) {
            const int q0 = wn * 32 + nt * 8 + (lane & 3) * 2;
            *(float2*)&S[r0 * SSTRIDE + q0]       = make_float2(acc[mt][nt][0], acc[mt][nt][1]);
            *(float2*)&S[(r0 + 8) * SSTRIDE + q0] = make_float2(acc[mt][nt][2], acc[mt][nt][3]);
        }
    }
    __syncthreads();

    float4 bq4 = *(const float4*)&sm_bq[lane * 4];
    #pragma unroll
    for (int r = 0; r < 8; r++) {
        const int row = wid * 8 + r;
        float4 v = *(const float4*)&S[row * SSTRIDE + lane * 4];
        float a = sm_a[row];
        v.x += a + bq4.x; v.y += a + bq4.y; v.z += a + bq4.z; v.w += a + bq4.w;
        float m = fmaxf(fmaxf(v.x, v.y), fmaxf(v.z, v.w));
        #pragma unroll
        for (int o = 16; o; o >>= 1) m = fmaxf(m, __shfl_xor_sync(0xffffffffu, m, o));
        *(float4*)(g_sim + ((size_t)(b * C + cb * 64 + row)) * Q + lane * 4) = v;
        if (lane == 0) g_smax[b * C + cb * 64 + row] = m;
    }
}

// ================= K2: column softmax -> dist hi/lo images =================
__global__ void k_colstats(const int* __restrict__ qmask) {
    const int b  = blockIdx.y;
    const int tx = threadIdx.x, ty = threadIdx.y;
    const int q  = blockIdx.x * 32 + tx;
    const int qm = qmask[b * Q + q];
    __shared__ float red[8][32];
    float m = -3.4e38f;
    for (int c = ty; c < C; c += 8) {
        float v = g_sim[((size_t)(b * C + c)) * Q + q];
        m = fmaxf(m, qm ? v : NEGBIG);
    }
    red[ty][tx] = m;
    __syncthreads();
    if (ty == 0) {
        #pragma unroll
        for (int k = 1; k < 8; k++) m = fmaxf(m, red[k][tx]);
        red[0][tx] = m;
    }
    __syncthreads();
    m = red[0][tx];
    __syncthreads();
    float s = 0.f;
    for (int c = ty; c < C; c += 8) {
        float v = g_sim[((size_t)(b * C + c)) * Q + q];
        s += expf((qm ? v : NEGBIG) - m);
    }
    red[ty][tx] = s;
    __syncthreads();
    if (ty == 0) {
        #pragma unroll
        for (int k = 1; k < 8; k++) s += red[k][tx];
        red[0][tx] = 1.f / s;
    }
    __syncthreads();
    const float rs = red[0][tx];
    // pass 3: write dist hi/lo images
    for (int c = ty; c < C; c += 8) {
        size_t idx = ((size_t)(b * C + c)) * Q + q;
        float v = g_sim[idx];
        float x = expf((qm ? v : NEGBIG) - m) * rs;
        __nv_bfloat16 h = __float2bfloat16(x);
        __nv_bfloat16 l = __float2bfloat16(x - __bfloat162float(h));
        g_Dh[idx] = h;
        g_Dl[idx] = l;
    }
}

// ================= K3: c_dash weights =================
__global__ __launch_bounds__(512) void k_cweights(const int* __restrict__ cmask) {
    const int b = blockIdx.x;
    const int t = threadIdx.x;
    __shared__ float red[512];
    float ms = cmask[b * C + t] ? g_smax[b * C + t] : NEGBIG;
    red[t] = ms;
    __syncthreads();
    for (int o = 256; o; o >>= 1) {
        if (t < o) red[t] = fmaxf(red[t], red[t + o]);
        __syncthreads();
    }
    float M = red[0];
    __syncthreads();
    float e = expf(ms - M);
    red[t] = e;
    __syncthreads();
    for (int o = 256; o; o >>= 1) {
        if (t < o) red[t] += red[t + o];
        __syncthreads();
    }
    g_cdw[b * C + t] = e / red[0];
}

// ================= K4: c_dash =================
__global__ __launch_bounds__(256) void k_cdash(const float* __restrict__ cont) {
    const int b = blockIdx.y, d0 = blockIdx.x * 64;
    const int t = threadIdx.x;
    const int dl = t & 63, cs = t >> 6;
    __shared__ float w[512];
    __shared__ float red[4][64];
    for (int c = t; c < 512; c += 256) w[c] = g_cdw[b * C + c];
    __syncthreads();
    float acc = 0.f;
    const float* base = cont + ((size_t)(b * C + cs * 128)) * D + d0 + dl;
    const float* wp = &w[cs * 128];
    #pragma unroll 4
    for (int c = 0; c < 128; c++) acc += wp[c] * base[(size_t)c * D];
    red[cs][dl] = acc;
    __syncthreads();
    if (t < 64)
        g_cdash[b * D + d0 + t] = (red[0][t] + red[1][t]) + (red[2][t] + red[3][t]);
}

// ================= K5: c2q GEMM (pure-copy mainloop) + epilogue =================
__global__ __launch_bounds__(256, 2) void k_c2q_mma(const float* __restrict__ cont,
                                                    float* __restrict__ out) {
    __shared__ char buf[64 * SSTRIDE * 4];   // A/B tiles, then staging overlay
    __shared__ float sm_cd[128];
    __nv_bfloat16 (*Ah)[40]  = (__nv_bfloat16 (*)[40])(buf);
    __nv_bfloat16 (*Al)[40]  = (__nv_bfloat16 (*)[40])(buf + 5120);
    __nv_bfloat16 (*Bh)[136] = (__nv_bfloat16 (*)[136])(buf + 10240);
    __nv_bfloat16 (*Bl)[136] = (__nv_bfloat16 (*)[136])(buf + 10240 + 8704);
    float* S = (float*)buf;

    const int cb = blockIdx.x, dt = blockIdx.y, b = blockIdx.z;
    const int t = threadIdx.x, lane = t & 31, wid = t >> 5;
    const int wm = wid & 1, wn = wid >> 1;

    if (t < 128) sm_cd[t] = g_cdash[b * D + dt * 128 + t];

    const __nv_bfloat16* Dh = g_Dh + ((size_t)(b * C + cb * 64)) * Q;
    const __nv_bfloat16* Dl = g_Dl + ((size_t)(b * C + cb * 64)) * Q;
    const __nv_bfloat16* Qh = g_Qh + ((size_t)b * Q) * D + dt * 128;
    const __nv_bfloat16* Ql = g_Ql + ((size_t)b * Q) * D + dt * 128;

    float acc[2][4][4];
    #pragma unroll
    for (int i = 0; i < 2; i++)
        #pragma unroll
        for (int j = 0; j < 4; j++)
            #pragma unroll
            for (int k = 0; k < 4; k++) acc[i][j][k] = 0.f;

    const int ar = t >> 2, acl = t & 3;     // A copy: 64 rows x 32 cols
    #pragma unroll
    for (int k0 = 0; k0 < Q; k0 += 32) {
        if (k0) __syncthreads();
        *(uint4*)&Ah[ar][acl * 8] = *(const uint4*)(Dh + (size_t)ar * Q + k0 + acl * 8);
        *(uint4*)&Al[ar][acl * 8] = *(const uint4*)(Dl + (size_t)ar * Q + k0 + acl * 8);
        #pragma unroll
        for (int i = 0; i < 2; i++) {
            int idx = t + i * 256;
            int r = idx >> 4, cl = idx & 15;
            *(uint4*)&Bh[r][cl * 8] = *(const uint4*)(Qh + (size_t)(k0 + r) * D + cl * 8);
            *(uint4*)&Bl[r][cl * 8] = *(const uint4*)(Ql + (size_t)(k0 + r) * D + cl * 8);
        }
        __syncthreads();
        #pragma unroll
        for (int kk = 0; kk < 2; kk++) {
            const int kb = kk * 16;
            unsigned afh[2][4], afl[2][4];
            #pragma unroll
            for (int mt = 0; mt < 2; mt++) {
                ldm_x4(afh[mt], &Ah[wm * 32 + mt * 16 + (lane & 15)][kb + (lane >> 4) * 8]);
                ldm_x4(afl[mt], &Al[wm * 32 + mt * 16 + (lane & 15)][kb + (lane >> 4) * 8]);
            }
            #pragma unroll
            for (int ng = 0; ng < 2; ng++) {
                unsigned bfh[4], bfl[4];
                ldm_x4t(bfh, &Bh[kb + (lane & 15)][wn * 32 + ng * 16 + (lane >> 4) * 8]);
                ldm_x4t(bfl, &Bl[kb + (lane & 15)][wn * 32 + ng * 16 + (lane >> 4) * 8]);
                #pragma unroll
                for (int h = 0; h < 2; h++) {
                    const int nt = ng * 2 + h;
                    #pragma unroll
                    for (int mt = 0; mt < 2; mt++) {
                        mma_bf16(acc[mt][nt], afh[mt], bfh[2 * h], bfh[2 * h + 1]);
                        mma_bf16(acc[mt][nt], afh[mt], bfl[2 * h], bfl[2 * h + 1]);
                        mma_bf16(acc[mt][nt], afl[mt], bfh[2 * h], bfh[2 * h + 1]);
                    }
                }
            }
        }
    }
    __syncthreads();

    // stage accumulators
    #pragma unroll
    for (int mt = 0; mt < 2; mt++) {
        const int r0 = wm * 32 + mt * 16 + (lane >> 2);
        #pragma unroll
        for (int nt = 0; nt < 4; nt++) {
            const int d0 = wn * 32 + nt * 8 + (lane & 3) * 2;
            *(float2*)&S[r0 * SSTRIDE + d0]       = make_float2(acc[mt][nt][0], acc[mt][nt][1]);
            *(float2*)&S[(r0 + 8) * SSTRIDE + d0] = make_float2(acc[mt][nt][2], acc[mt][nt][3]);
        }
    }
    __syncthreads();

    float4 cd = *(const float4*)&sm_cd[lane * 4];
    #pragma unroll
    for (int r = 0; r < 8; r++) {
        const int row = wid * 8 + r;
        const int c = cb * 64 + row;
        float4 cq = *(const float4*)&S[row * SSTRIDE + lane * 4];
        float4 ct = *(const float4*)(cont + ((size_t)(b * C + c)) * D + dt * 128 + lane * 4);
        float4 m1 = make_float4(ct.x * cq.x, ct.y * cq.y, ct.z * cq.z, ct.w * cq.w);
        float4 m2 = make_float4(ct.x * cd.x, ct.y * cd.y, ct.z * cd.z, ct.w * cd.w);
        float* ob = out + ((size_t)(b * C + c)) * OD + dt * 128 + lane * 4;
        *(float4*)(ob)         = ct;
        *(float4*)(ob + D)     = cq;
        *(float4*)(ob + 2 * D) = m1;
        *(float4*)(ob + 3 * D) = m2;
    }
}

// ---------------- launch ----------------
extern "C" void kernel_launch(void* const* d_in, const int* in_sizes, int n_in,
                              void* d_out, int out_size) {
    const float* cont  = (const float*)d_in[0];
    const int*   cmask = (const int*)d_in[1];
    const float* ques  = (const float*)d_in[2];
    const int*   qmask = (const int*)d_in[3];
    const float* SW    = (const float*)d_in[4];
    float* out = (float*)d_out;
    (void)in_sizes; (void)n_in; (void)out_size;

    {                           k_convQ<<<B, 256>>>(ques, SW); }
    {   dim3 g(C / 64, B);      k_sim_mma<<<g, 256>>>(cont, SW); }
    {   dim3 g(Q / 32, B);      dim3 th(32, 8); k_colstats<<<g, th>>>(qmask); }
    {                           k_cweights<<<B, 512>>>(cmask); }
    {   dim3 g(D / 64, B);      k_cdash<<<g, 256>>>(cont); }
    {   dim3 g(C / 64, 6, B);   k_c2q_mma<<<g, 256>>>(cont, out); }
}

// round 11
// speedup vs baseline: 1.1350x; 1.0338x over previous
#include <cuda_runtime.h>
#include <cuda_bf16.h>
#include <math.h>
#include <stdint.h>

#define B 32
#define C 512
#define Q 128
#define D 768
#define OD (4*D)
#define NEGBIG (-1e30f)

// ---------------- scratch ----------------
__device__ float g_sim [(size_t)B*C*Q];
__device__ float g_smax[B*C];
__device__ float g_cdw [B*C];
__device__ float g_cdash[B*D];
__device__ float g_bq  [B*Q];
__device__ __nv_bfloat16 g_Qh[(size_t)B*Q*D];
__device__ __nv_bfloat16 g_Ql[(size_t)B*Q*D];
__device__ __nv_bfloat16 g_Dh[(size_t)B*C*Q];
__device__ __nv_bfloat16 g_Dl[(size_t)B*C*Q];

// ---------------- helpers ----------------
__device__ __forceinline__ unsigned smem_u32(const void* p) {
    unsigned a;
    asm("{ .reg .u64 tmp; cvta.to.shared.u64 tmp, %1; cvt.u32.u64 %0, tmp; }" : "=r"(a) : "l"(p));
    return a;
}
__device__ __forceinline__ void cp16(void* dst, const void* src) {
    unsigned d = smem_u32(dst);
    asm volatile("cp.async.cg.shared.global [%0], [%1], 16;" :: "r"(d), "l"(src));
}
#define CP_COMMIT() asm volatile("cp.async.commit_group;" ::: "memory")
#define CP_WAIT(n)  asm volatile("cp.async.wait_group %0;" :: "n"(n) : "memory")
__device__ __forceinline__ void ldm_x4(unsigned* r, const void* p) {
    unsigned a = smem_u32(p);
    asm volatile("ldmatrix.sync.aligned.m8n8.x4.shared.b16 {%0,%1,%2,%3}, [%4];"
        : "=r"(r[0]), "=r"(r[1]), "=r"(r[2]), "=r"(r[3]) : "r"(a));
}
__device__ __forceinline__ void ldm_x4t(unsigned* r, const void* p) {
    unsigned a = smem_u32(p);
    asm volatile("ldmatrix.sync.aligned.m8n8.x4.trans.shared.b16 {%0,%1,%2,%3}, [%4];"
        : "=r"(r[0]), "=r"(r[1]), "=r"(r[2]), "=r"(r[3]) : "r"(a));
}
__device__ __forceinline__ void mma_bf16(float* d, const unsigned* a, unsigned b0, unsigned b1) {
    asm volatile("mma.sync.aligned.m16n8k16.row.col.f32.bf16.bf16.f32 "
        "{%0,%1,%2,%3}, {%4,%5,%6,%7}, {%8,%9}, {%0,%1,%2,%3};"
        : "+f"(d[0]), "+f"(d[1]), "+f"(d[2]), "+f"(d[3])
        : "r"(a[0]), "r"(a[1]), "r"(a[2]), "r"(a[3]), "r"(b0), "r"(b1));
}
__device__ __forceinline__ void split2(float x0, float x1, unsigned& h, unsigned& l) {
    __nv_bfloat16 h0 = __float2bfloat16(x0), h1 = __float2bfloat16(x1);
    float r0 = x0 - __bfloat162float(h0), r1 = x1 - __bfloat162float(h1);
    __nv_bfloat16 l0 = __float2bfloat16(r0), l1 = __float2bfloat16(r1);
    unsigned short a0 = *(unsigned short*)&h0, a1 = *(unsigned short*)&h1;
    unsigned short b0 = *(unsigned short*)&l0, b1 = *(unsigned short*)&l1;
    h = (unsigned)a0 | ((unsigned)a1 << 16);
    l = (unsigned)b0 | ((unsigned)b1 << 16);
}

#define SSTRIDE 132

// ================= K0: ques -> bf16 hi/lo images + q.w2 =================
__global__ __launch_bounds__(256) void k_convQ(const float* __restrict__ ques,
                                               const float* __restrict__ SW) {
    const int b = blockIdx.x;
    const int t = threadIdx.x;
    const int row = t >> 1, half = t & 1;
    const float* src = ques + ((size_t)(b * Q + row)) * D + half * 384;
    const float* w2 = SW + D + half * 384;
    __nv_bfloat16* dh = g_Qh + ((size_t)(b * Q + row)) * D + half * 384;
    __nv_bfloat16* dl = g_Ql + ((size_t)(b * Q + row)) * D + half * 384;
    float acc = 0.f;
    #pragma unroll 4
    for (int g = 0; g < 48; g++) {
        float4 v0 = *(const float4*)(src + g * 8);
        float4 v1 = *(const float4*)(src + g * 8 + 4);
        float4 w0 = *(const float4*)(w2 + g * 8);
        float4 w1 = *(const float4*)(w2 + g * 8 + 4);
        acc += v0.x*w0.x + v0.y*w0.y + v0.z*w0.z + v0.w*w0.w
             + v1.x*w1.x + v1.y*w1.y + v1.z*w1.z + v1.w*w1.w;
        unsigned h0, l0, h1, l1, h2, l2, h3, l3;
        split2(v0.x, v0.y, h0, l0);
        split2(v0.z, v0.w, h1, l1);
        split2(v1.x, v1.y, h2, l2);
        split2(v1.z, v1.w, h3, l3);
        *(uint4*)(dh + g * 8) = make_uint4(h0, h1, h2, h3);
        *(uint4*)(dl + g * 8) = make_uint4(l0, l1, l2, l3);
    }
    acc += __shfl_xor_sync(0xffffffffu, acc, 1);
    if (half == 0) g_bq[b * Q + row] = acc;
}

// ================= K1: sim GEMM (cp.async double-buffered) =================
// dynamic smem layout: Ah2 [2][64][40] @0, Al2 @10240, Bh2 [2][128][40] @20480, Bl2 @40960
#define SIM_SMEM 61440
__global__ __launch_bounds__(256, 2) void k_sim_mma(const float* __restrict__ cont,
                                                    const float* __restrict__ SW) {
    extern __shared__ char dbuf[];
    __shared__ float sm_a[64], sm_bq[128];
    float* S = (float*)dbuf;

    const int cb = blockIdx.x, b = blockIdx.y;
    const int t = threadIdx.x, lane = t & 31, wid = t >> 5;
    const int wm = wid & 1, wn = wid >> 1;
    const int arow = t >> 2, acol = (t & 3) * 8;

    if (t < 128) sm_bq[t] = g_bq[b * Q + t];

    const float* Ag = cont + ((size_t)(b * C + cb * 64 + arow)) * D + acol;
    const __nv_bfloat16* Qh = g_Qh + ((size_t)b * Q) * D;
    const __nv_bfloat16* Ql = g_Ql + ((size_t)b * Q) * D;
    const float* w1 = SW;
    const float* w3 = SW + 2 * D;

    float acc[2][4][4];
    #pragma unroll
    for (int i = 0; i < 2; i++)
        #pragma unroll
        for (int j = 0; j < 4; j++)
            #pragma unroll
            for (int k = 0; k < 4; k++) acc[i][j][k] = 0.f;

    float a_part = 0.f;
    float4 ra[2];

    // helpers to address buffers
    auto AhB = [&](int s) { return (__nv_bfloat16(*)[40])(dbuf + s * 5120); };
    auto AlB = [&](int s) { return (__nv_bfloat16(*)[40])(dbuf + 10240 + s * 5120); };
    auto BhB = [&](int s) { return (__nv_bfloat16(*)[40])(dbuf + 20480 + s * 10240); };
    auto BlB = [&](int s) { return (__nv_bfloat16(*)[40])(dbuf + 40960 + s * 10240); };

    // split+STS A for chunk k0 into buffer s (also accumulates a_part)
    auto splitA = [&](int k0, int s) {
        __nv_bfloat16 (*Ah)[40] = AhB(s);
        __nv_bfloat16 (*Al)[40] = AlB(s);
        #pragma unroll
        for (int j = 0; j < 2; j++) {
            int col = acol + j * 4;
            float4 w3v = *(const float4*)(w3 + k0 + col);
            float4 w1v = *(const float4*)(w1 + k0 + col);
            a_part += ra[j].x * w1v.x + ra[j].y * w1v.y + ra[j].z * w1v.z + ra[j].w * w1v.w;
            unsigned h0, l0, h1, l1;
            split2(ra[j].x * w3v.x, ra[j].y * w3v.y, h0, l0);
            split2(ra[j].z * w3v.z, ra[j].w * w3v.w, h1, l1);
            *(unsigned*)&Ah[arow][col]     = h0;  *(unsigned*)&Al[arow][col]     = l0;
            *(unsigned*)&Ah[arow][col + 2] = h1;  *(unsigned*)&Al[arow][col + 2] = l1;
        }
    };
    auto issueB = [&](int k0, int s) {
        __nv_bfloat16 (*Bh)[40] = BhB(s);
        __nv_bfloat16 (*Bl)[40] = BlB(s);
        #pragma unroll
        for (int i = 0; i < 2; i++) {
            int idx = t + i * 256;
            int r = idx >> 2, cl = idx & 3;
            cp16(&Bh[r][cl * 8], Qh + (size_t)r * D + k0 + cl * 8);
            cp16(&Bl[r][cl * 8], Ql + (size_t)r * D + k0 + cl * 8);
        }
    };

    // prologue
    ra[0] = *(const float4*)(Ag);     ra[1] = *(const float4*)(Ag + 4);
    issueB(0, 0);  CP_COMMIT();
    splitA(0, 0);
    ra[0] = *(const float4*)(Ag + 32); ra[1] = *(const float4*)(Ag + 36);
    issueB(32, 1); CP_COMMIT();
    splitA(32, 1);
    ra[0] = *(const float4*)(Ag + 64); ra[1] = *(const float4*)(Ag + 68);
    CP_WAIT(1);
    __syncthreads();

    const int NK = D / 32;   // 24
    for (int k = 0; k < NK; k++) {
        const int cur = k & 1;
        // MMA on current buffer
        __nv_bfloat16 (*Ah)[40] = AhB(cur);
        __nv_bfloat16 (*Al)[40] = AlB(cur);
        __nv_bfloat16 (*Bh)[40] = BhB(cur);
        __nv_bfloat16 (*Bl)[40] = BlB(cur);
        #pragma unroll
        for (int kk = 0; kk < 2; kk++) {
            const int kb = kk * 16;
            unsigned afh[2][4], afl[2][4];
            #pragma unroll
            for (int mt = 0; mt < 2; mt++) {
                ldm_x4(afh[mt], &Ah[wm * 32 + mt * 16 + (lane & 15)][kb + (lane >> 4) * 8]);
                ldm_x4(afl[mt], &Al[wm * 32 + mt * 16 + (lane & 15)][kb + (lane >> 4) * 8]);
            }
            #pragma unroll
            for (int ng = 0; ng < 2; ng++) {
                unsigned bfh[4], bfl[4];
                ldm_x4(bfh, &Bh[wn * 32 + ng * 16 + (lane & 15)][kb + (lane >> 4) * 8]);
                ldm_x4(bfl, &Bl[wn * 32 + ng * 16 + (lane & 15)][kb + (lane >> 4) * 8]);
                #pragma unroll
                for (int h = 0; h < 2; h++) {
                    const int nt = ng * 2 + h;
                    #pragma unroll
                    for (int mt = 0; mt < 2; mt++) {
                        mma_bf16(acc[mt][nt], afh[mt], bfh[h], bfh[2 + h]);
                        mma_bf16(acc[mt][nt], afh[mt], bfl[h], bfl[2 + h]);
                        mma_bf16(acc[mt][nt], afl[mt], bfh[h], bfh[2 + h]);
                    }
                }
            }
        }
        __syncthreads();   // all reads of buf[cur] done
        if (k + 2 < NK) {
            issueB((k + 2) * 32, cur); CP_COMMIT();
            splitA((k + 2) * 32, cur);
            if (k + 3 < NK) {
                ra[0] = *(const float4*)(Ag + (k + 3) * 32);
                ra[1] = *(const float4*)(Ag + (k + 3) * 32 + 4);
            }
        }
        if (k + 1 < NK) {
            if (k + 2 < NK) { CP_WAIT(1); } else { CP_WAIT(0); }
            __syncthreads();
        }
    }

    a_part += __shfl_xor_sync(0xffffffffu, a_part, 1);
    a_part += __shfl_xor_sync(0xffffffffu, a_part, 2);
    if ((t & 3) == 0) sm_a[arow] = a_part;
    __syncthreads();

    #pragma unroll
    for (int mt = 0; mt < 2; mt++) {
        const int r0 = wm * 32 + mt * 16 + (lane >> 2);
        #pragma unroll
        for (int nt = 0; nt < 4; nt++) {
            const int q0 = wn * 32 + nt * 8 + (lane & 3) * 2;
            *(float2*)&S[r0 * SSTRIDE + q0]       = make_float2(acc[mt][nt][0], acc[mt][nt][1]);
            *(float2*)&S[(r0 + 8) * SSTRIDE + q0] = make_float2(acc[mt][nt][2], acc[mt][nt][3]);
        }
    }
    __syncthreads();

    float4 bq4 = *(const float4*)&sm_bq[lane * 4];
    #pragma unroll
    for (int r = 0; r < 8; r++) {
        const int row = wid * 8 + r;
        float4 v = *(const float4*)&S[row * SSTRIDE + lane * 4];
        float a = sm_a[row];
        v.x += a + bq4.x; v.y += a + bq4.y; v.z += a + bq4.z; v.w += a + bq4.w;
        float m = fmaxf(fmaxf(v.x, v.y), fmaxf(v.z, v.w));
        #pragma unroll
        for (int o = 16; o; o >>= 1) m = fmaxf(m, __shfl_xor_sync(0xffffffffu, m, o));
        *(float4*)(g_sim + ((size_t)(b * C + cb * 64 + row)) * Q + lane * 4) = v;
        if (lane == 0) g_smax[b * C + cb * 64 + row] = m;
    }
}

// ================= K2: column softmax -> dist hi/lo images =================
__global__ void k_colstats(const int* __restrict__ qmask) {
    const int b  = blockIdx.y;
    const int tx = threadIdx.x, ty = threadIdx.y;
    const int q  = blockIdx.x * 32 + tx;
    const int qm = qmask[b * Q + q];
    __shared__ float red[8][32];
    float m = -3.4e38f;
    for (int c = ty; c < C; c += 8) {
        float v = g_sim[((size_t)(b * C + c)) * Q + q];
        m = fmaxf(m, qm ? v : NEGBIG);
    }
    red[ty][tx] = m;
    __syncthreads();
    if (ty == 0) {
        #pragma unroll
        for (int k = 1; k < 8; k++) m = fmaxf(m, red[k][tx]);
        red[0][tx] = m;
    }
    __syncthreads();
    m = red[0][tx];
    __syncthreads();
    float s = 0.f;
    for (int c = ty; c < C; c += 8) {
        float v = g_sim[((size_t)(b * C + c)) * Q + q];
        s += expf((qm ? v : NEGBIG) - m);
    }
    red[ty][tx] = s;
    __syncthreads();
    if (ty == 0) {
        #pragma unroll
        for (int k = 1; k < 8; k++) s += red[k][tx];
        red[0][tx] = 1.f / s;
    }
    __syncthreads();
    const float rs = red[0][tx];
    for (int c = ty; c < C; c += 8) {
        size_t idx = ((size_t)(b * C + c)) * Q + q;
        float v = g_sim[idx];
        float x = expf((qm ? v : NEGBIG) - m) * rs;
        __nv_bfloat16 h = __float2bfloat16(x);
        __nv_bfloat16 l = __float2bfloat16(x - __bfloat162float(h));
        g_Dh[idx] = h;
        g_Dl[idx] = l;
    }
}

// ================= K3: c_dash weights =================
__global__ __launch_bounds__(512) void k_cweights(const int* __restrict__ cmask) {
    const int b = blockIdx.x;
    const int t = threadIdx.x;
    __shared__ float red[512];
    float ms = cmask[b * C + t] ? g_smax[b * C + t] : NEGBIG;
    red[t] = ms;
    __syncthreads();
    for (int o = 256; o; o >>= 1) {
        if (t < o) red[t] = fmaxf(red[t], red[t + o]);
        __syncthreads();
    }
    float M = red[0];
    __syncthreads();
    float e = expf(ms - M);
    red[t] = e;
    __syncthreads();
    for (int o = 256; o; o >>= 1) {
        if (t < o) red[t] += red[t + o];
        __syncthreads();
    }
    g_cdw[b * C + t] = e / red[0];
}

// ================= K4: c_dash =================
__global__ __launch_bounds__(256) void k_cdash(const float* __restrict__ cont) {
    const int b = blockIdx.y, d0 = blockIdx.x * 64;
    const int t = threadIdx.x;
    const int dl = t & 63, cs = t >> 6;
    __shared__ float w[512];
    __shared__ float red[4][64];
    for (int c = t; c < 512; c += 256) w[c] = g_cdw[b * C + c];
    __syncthreads();
    float acc = 0.f;
    const float* base = cont + ((size_t)(b * C + cs * 128)) * D + d0 + dl;
    const float* wp = &w[cs * 128];
    #pragma unroll 4
    for (int c = 0; c < 128; c++) acc += wp[c] * base[(size_t)c * D];
    red[cs][dl] = acc;
    __syncthreads();
    if (t < 64)
        g_cdash[b * D + d0 + t] = (red[0][t] + red[1][t]) + (red[2][t] + red[3][t]);
}

// ================= K5: c2q GEMM (cp.async double-buffered) + epilogue =================
// dynamic smem: Ah2 [2][64][40] @0, Al2 @10240, Bh2 [2][32][136] @20480, Bl2 @37888
#define C2Q_SMEM 55296
__global__ __launch_bounds__(256, 2) void k_c2q_mma(const float* __restrict__ cont,
                                                    float* __restrict__ out) {
    extern __shared__ char dbuf[];
    __shared__ float sm_cd[128];
    float* S = (float*)dbuf;

    const int cb = blockIdx.x, dt = blockIdx.y, b = blockIdx.z;
    const int t = threadIdx.x, lane = t & 31, wid = t >> 5;
    const int wm = wid & 1, wn = wid >> 1;

    if (t < 128) sm_cd[t] = g_cdash[b * D + dt * 128 + t];

    const __nv_bfloat16* Dh = g_Dh + ((size_t)(b * C + cb * 64)) * Q;
    const __nv_bfloat16* Dl = g_Dl + ((size_t)(b * C + cb * 64)) * Q;
    const __nv_bfloat16* Qh = g_Qh + ((size_t)b * Q) * D + dt * 128;
    const __nv_bfloat16* Ql = g_Ql + ((size_t)b * Q) * D + dt * 128;

    auto AhB = [&](int s) { return (__nv_bfloat16(*)[40])(dbuf + s * 5120); };
    auto AlB = [&](int s) { return (__nv_bfloat16(*)[40])(dbuf + 10240 + s * 5120); };
    auto BhB = [&](int s) { return (__nv_bfloat16(*)[136])(dbuf + 20480 + s * 8704); };
    auto BlB = [&](int s) { return (__nv_bfloat16(*)[136])(dbuf + 37888 + s * 8704); };

    const int ar = t >> 2, acl = t & 3;
    auto issueChunk = [&](int k0, int s) {
        __nv_bfloat16 (*Ah)[40] = AhB(s);
        __nv_bfloat16 (*Al)[40] = AlB(s);
        cp16(&Ah[ar][acl * 8], Dh + (size_t)ar * Q + k0 + acl * 8);
        cp16(&Al[ar][acl * 8], Dl + (size_t)ar * Q + k0 + acl * 8);
        __nv_bfloat16 (*Bh)[136] = BhB(s);
        __nv_bfloat16 (*Bl)[136] = BlB(s);
        #pragma unroll
        for (int i = 0; i < 2; i++) {
            int idx = t + i * 256;
            int r = idx >> 4, cl = idx & 15;
            cp16(&Bh[r][cl * 8], Qh + (size_t)(k0 + r) * D + cl * 8);
            cp16(&Bl[r][cl * 8], Ql + (size_t)(k0 + r) * D + cl * 8);
        }
    };

    float acc[2][4][4];
    #pragma unroll
    for (int i = 0; i < 2; i++)
        #pragma unroll
        for (int j = 0; j < 4; j++)
            #pragma unroll
            for (int k = 0; k < 4; k++) acc[i][j][k] = 0.f;

    issueChunk(0, 0);  CP_COMMIT();
    issueChunk(32, 1); CP_COMMIT();
    CP_WAIT(1);
    __syncthreads();

    #pragma unroll
    for (int k = 0; k < 4; k++) {
        const int cur = k & 1;
        __nv_bfloat16 (*Ah)[40]  = AhB(cur);
        __nv_bfloat16 (*Al)[40]  = AlB(cur);
        __nv_bfloat16 (*Bh)[136] = BhB(cur);
        __nv_bfloat16 (*Bl)[136] = BlB(cur);
        #pragma unroll
        for (int kk = 0; kk < 2; kk++) {
            const int kb = kk * 16;
            unsigned afh[2][4], afl[2][4];
            #pragma unroll
            for (int mt = 0; mt < 2; mt++) {
                ldm_x4(afh[mt], &Ah[wm * 32 + mt * 16 + (lane & 15)][kb + (lane >> 4) * 8]);
                ldm_x4(afl[mt], &Al[wm * 32 + mt * 16 + (lane & 15)][kb + (lane >> 4) * 8]);
            }
            #pragma unroll
            for (int ng = 0; ng < 2; ng++) {
                unsigned bfh[4], bfl[4];
                ldm_x4t(bfh, &Bh[kb + (lane & 15)][wn * 32 + ng * 16 + (lane >> 4) * 8]);
                ldm_x4t(bfl, &Bl[kb + (lane & 15)][wn * 32 + ng * 16 + (lane >> 4) * 8]);
                #pragma unroll
                for (int h = 0; h < 2; h++) {
                    const int nt = ng * 2 + h;
                    #pragma unroll
                    for (int mt = 0; mt < 2; mt++) {
                        mma_bf16(acc[mt][nt], afh[mt], bfh[2 * h], bfh[2 * h + 1]);
                        mma_bf16(acc[mt][nt], afh[mt], bfl[2 * h], bfl[2 * h + 1]);
                        mma_bf16(acc[mt][nt], afl[mt], bfh[2 * h], bfh[2 * h + 1]);
                    }
                }
            }
        }
        __syncthreads();
        if (k + 2 < 4) { issueChunk((k + 2) * 32, cur); CP_COMMIT(); }
        if (k + 1 < 4) {
            if (k + 2 < 4) { CP_WAIT(1); } else { CP_WAIT(0); }
            __syncthreads();
        }
    }

    // stage accumulators (S overlays buffers)
    #pragma unroll
    for (int mt = 0; mt < 2; mt++) {
        const int r0 = wm * 32 + mt * 16 + (lane >> 2);
        #pragma unroll
        for (int nt = 0; nt < 4; nt++) {
            const int d0 = wn * 32 + nt * 8 + (lane & 3) * 2;
            *(float2*)&S[r0 * SSTRIDE + d0]       = make_float2(acc[mt][nt][0], acc[mt][nt][1]);
            *(float2*)&S[(r0 + 8) * SSTRIDE + d0] = make_float2(acc[mt][nt][2], acc[mt][nt][3]);
        }
    }
    __syncthreads();

    float4 cd = *(const float4*)&sm_cd[lane * 4];
    #pragma unroll
    for (int r = 0; r < 8; r++) {
        const int row = wid * 8 + r;
        const int c = cb * 64 + row;
        float4 cq = *(const float4*)&S[row * SSTRIDE + lane * 4];
        float4 ct = *(const float4*)(cont + ((size_t)(b * C + c)) * D + dt * 128 + lane * 4);
        float4 m1 = make_float4(ct.x * cq.x, ct.y * cq.y, ct.z * cq.z, ct.w * cq.w);
        float4 m2 = make_float4(ct.x * cd.x, ct.y * cd.y, ct.z * cd.z, ct.w * cd.w);
        float* ob = out + ((size_t)(b * C + c)) * OD + dt * 128 + lane * 4;
        *(float4*)(ob)         = ct;
        *(float4*)(ob + D)     = cq;
        *(float4*)(ob + 2 * D) = m1;
        *(float4*)(ob + 3 * D) = m2;
    }
}

// ---------------- launch ----------------
extern "C" void kernel_launch(void* const* d_in, const int* in_sizes, int n_in,
                              void* d_out, int out_size) {
    const float* cont  = (const float*)d_in[0];
    const int*   cmask = (const int*)d_in[1];
    const float* ques  = (const float*)d_in[2];
    const int*   qmask = (const int*)d_in[3];
    const float* SW    = (const float*)d_in[4];
    float* out = (float*)d_out;
    (void)in_sizes; (void)n_in; (void)out_size;

    cudaFuncSetAttribute(k_sim_mma, cudaFuncAttributeMaxDynamicSharedMemorySize, SIM_SMEM);
    cudaFuncSetAttribute(k_c2q_mma, cudaFuncAttributeMaxDynamicSharedMemorySize, C2Q_SMEM);

    {                           k_convQ<<<B, 256>>>(ques, SW); }
    {   dim3 g(C / 64, B);      k_sim_mma<<<g, 256, SIM_SMEM>>>(cont, SW); }
    {   dim3 g(Q / 32, B);      dim3 th(32, 8); k_colstats<<<g, th>>>(qmask); }
    {                           k_cweights<<<B, 512>>>(cmask); }
    {   dim3 g(D / 64, B);      k_cdash<<<g, 256>>>(cont); }
    {   dim3 g(C / 64, 6, B);   k_c2q_mma<<<g, 256, C2Q_SMEM>>>(cont, out); }
}

// round 12
// speedup vs baseline: 1.2460x; 1.0979x over previous
#include <cuda_runtime.h>
#include <cuda_bf16.h>
#include <math.h>
#include <stdint.h>

#define B 32
#define C 512
#define Q 128
#define D 768
#define OD (4*D)
#define NEGBIG (-1e30f)

// ---------------- scratch ----------------
__device__ float g_sim [(size_t)B*C*Q];
__device__ float g_smax[B*C];
__device__ float g_cdash[B*D];
__device__ float g_bq  [B*Q];
__device__ __nv_bfloat16 g_Qh[(size_t)B*Q*D];
__device__ __nv_bfloat16 g_Ql[(size_t)B*Q*D];
__device__ __nv_bfloat16 g_Dh[(size_t)B*C*Q];
__device__ __nv_bfloat16 g_Dl[(size_t)B*C*Q];

// ---------------- helpers ----------------
__device__ __forceinline__ unsigned smem_u32(const void* p) {
    unsigned a;
    asm("{ .reg .u64 tmp; cvta.to.shared.u64 tmp, %1; cvt.u32.u64 %0, tmp; }" : "=r"(a) : "l"(p));
    return a;
}
__device__ __forceinline__ void cp16(void* dst, const void* src) {
    unsigned d = smem_u32(dst);
    asm volatile("cp.async.cg.shared.global [%0], [%1], 16;" :: "r"(d), "l"(src));
}
#define CP_COMMIT() asm volatile("cp.async.commit_group;" ::: "memory")
#define CP_WAIT(n)  asm volatile("cp.async.wait_group %0;" :: "n"(n) : "memory")
__device__ __forceinline__ void ldm_x4(unsigned* r, const void* p) {
    unsigned a = smem_u32(p);
    asm volatile("ldmatrix.sync.aligned.m8n8.x4.shared.b16 {%0,%1,%2,%3}, [%4];"
        : "=r"(r[0]), "=r"(r[1]), "=r"(r[2]), "=r"(r[3]) : "r"(a));
}
__device__ __forceinline__ void ldm_x4t(unsigned* r, const void* p) {
    unsigned a = smem_u32(p);
    asm volatile("ldmatrix.sync.aligned.m8n8.x4.trans.shared.b16 {%0,%1,%2,%3}, [%4];"
        : "=r"(r[0]), "=r"(r[1]), "=r"(r[2]), "=r"(r[3]) : "r"(a));
}
__device__ __forceinline__ void mma_bf16(float* d, const unsigned* a, unsigned b0, unsigned b1) {
    asm volatile("mma.sync.aligned.m16n8k16.row.col.f32.bf16.bf16.f32 "
        "{%0,%1,%2,%3}, {%4,%5,%6,%7}, {%8,%9}, {%0,%1,%2,%3};"
        : "+f"(d[0]), "+f"(d[1]), "+f"(d[2]), "+f"(d[3])
        : "r"(a[0]), "r"(a[1]), "r"(a[2]), "r"(a[3]), "r"(b0), "r"(b1));
}
__device__ __forceinline__ void split2(float x0, float x1, unsigned& h, unsigned& l) {
    __nv_bfloat16 h0 = __float2bfloat16(x0), h1 = __float2bfloat16(x1);
    float r0 = x0 - __bfloat162float(h0), r1 = x1 - __bfloat162float(h1);
    __nv_bfloat16 l0 = __float2bfloat16(r0), l1 = __float2bfloat16(r1);
    unsigned short a0 = *(unsigned short*)&h0, a1 = *(unsigned short*)&h1;
    unsigned short b0 = *(unsigned short*)&l0, b1 = *(unsigned short*)&l1;
    h = (unsigned)a0 | ((unsigned)a1 << 16);
    l = (unsigned)b0 | ((unsigned)b1 << 16);
}

#define SSTRIDE 132

// ================= K0: ques -> bf16 hi/lo images + q.w2 =================
__global__ __launch_bounds__(256) void k_convQ(const float* __restrict__ ques,
                                               const float* __restrict__ SW) {
    const int b = blockIdx.x;
    const int t = threadIdx.x;
    const int row = t >> 1, half = t & 1;
    const float* src = ques + ((size_t)(b * Q + row)) * D + half * 384;
    const float* w2 = SW + D + half * 384;
    __nv_bfloat16* dh = g_Qh + ((size_t)(b * Q + row)) * D + half * 384;
    __nv_bfloat16* dl = g_Ql + ((size_t)(b * Q + row)) * D + half * 384;
    float acc = 0.f;
    #pragma unroll 4
    for (int g = 0; g < 48; g++) {
        float4 v0 = *(const float4*)(src + g * 8);
        float4 v1 = *(const float4*)(src + g * 8 + 4);
        float4 w0 = *(const float4*)(w2 + g * 8);
        float4 w1 = *(const float4*)(w2 + g * 8 + 4);
        acc += v0.x*w0.x + v0.y*w0.y + v0.z*w0.z + v0.w*w0.w
             + v1.x*w1.x + v1.y*w1.y + v1.z*w1.z + v1.w*w1.w;
        unsigned h0, l0, h1, l1, h2, l2, h3, l3;
        split2(v0.x, v0.y, h0, l0);
        split2(v0.z, v0.w, h1, l1);
        split2(v1.x, v1.y, h2, l2);
        split2(v1.z, v1.w, h3, l3);
        *(uint4*)(dh + g * 8) = make_uint4(h0, h1, h2, h3);
        *(uint4*)(dl + g * 8) = make_uint4(l0, l1, l2, l3);
    }
    acc += __shfl_xor_sync(0xffffffffu, acc, 1);
    if (half == 0) g_bq[b * Q + row] = acc;
}

// ================= K1: sim GEMM (3-stage cp.async, 1 sync/chunk) =================
#define SIM_STAGE 30720
#define SIM_SMEM (3 * SIM_STAGE)   // 92160
__global__ __launch_bounds__(256, 2) void k_sim_mma(const float* __restrict__ cont,
                                                    const float* __restrict__ SW) {
    extern __shared__ char dbuf[];
    __shared__ float sm_a[64], sm_bq[128];
    float* S = (float*)dbuf;

    const int cb = blockIdx.x, b = blockIdx.y;
    const int t = threadIdx.x, lane = t & 31, wid = t >> 5;
    const int wm = wid & 1, wn = wid >> 1;
    const int arow = t >> 2, acol = (t & 3) * 8;

    if (t < 128) sm_bq[t] = g_bq[b * Q + t];

    const float* Ag = cont + ((size_t)(b * C + cb * 64 + arow)) * D + acol;
    const __nv_bfloat16* Qh = g_Qh + ((size_t)b * Q) * D;
    const __nv_bfloat16* Ql = g_Ql + ((size_t)b * Q) * D;
    const float* w1 = SW;
    const float* w3 = SW + 2 * D;

    float acc[2][4][4];
    #pragma unroll
    for (int i = 0; i < 2; i++)
        #pragma unroll
        for (int j = 0; j < 4; j++)
            #pragma unroll
            for (int k = 0; k < 4; k++) acc[i][j][k] = 0.f;

    float a_part = 0.f;
    float4 ra[2];

    auto AhB = [&](int s) { return (__nv_bfloat16(*)[40])(dbuf + s * SIM_STAGE); };
    auto AlB = [&](int s) { return (__nv_bfloat16(*)[40])(dbuf + s * SIM_STAGE + 5120); };
    auto BhB = [&](int s) { return (__nv_bfloat16(*)[40])(dbuf + s * SIM_STAGE + 10240); };
    auto BlB = [&](int s) { return (__nv_bfloat16(*)[40])(dbuf + s * SIM_STAGE + 20480); };

    auto splitA = [&](int k0, int s) {
        __nv_bfloat16 (*Ah)[40] = AhB(s);
        __nv_bfloat16 (*Al)[40] = AlB(s);
        #pragma unroll
        for (int j = 0; j < 2; j++) {
            int col = acol + j * 4;
            float4 w3v = *(const float4*)(w3 + k0 + col);
            float4 w1v = *(const float4*)(w1 + k0 + col);
            a_part += ra[j].x * w1v.x + ra[j].y * w1v.y + ra[j].z * w1v.z + ra[j].w * w1v.w;
            unsigned h0, l0, h1, l1;
            split2(ra[j].x * w3v.x, ra[j].y * w3v.y, h0, l0);
            split2(ra[j].z * w3v.z, ra[j].w * w3v.w, h1, l1);
            *(unsigned*)&Ah[arow][col]     = h0;  *(unsigned*)&Al[arow][col]     = l0;
            *(unsigned*)&Ah[arow][col + 2] = h1;  *(unsigned*)&Al[arow][col + 2] = l1;
        }
    };
    auto issueB = [&](int k0, int s) {
        __nv_bfloat16 (*Bh)[40] = BhB(s);
        __nv_bfloat16 (*Bl)[40] = BlB(s);
        #pragma unroll
        for (int i = 0; i < 2; i++) {
            int idx = t + i * 256;
            int r = idx >> 2, cl = idx & 3;
            cp16(&Bh[r][cl * 8], Qh + (size_t)r * D + k0 + cl * 8);
            cp16(&Bl[r][cl * 8], Ql + (size_t)r * D + k0 + cl * 8);
        }
    };

    const int NK = D / 32;   // 24
    // prologue: stages 0,1 filled
    ra[0] = *(const float4*)(Ag);      ra[1] = *(const float4*)(Ag + 4);
    issueB(0, 0);  CP_COMMIT();
    splitA(0, 0);
    ra[0] = *(const float4*)(Ag + 32); ra[1] = *(const float4*)(Ag + 36);
    issueB(32, 1); CP_COMMIT();
    splitA(32, 1);
    ra[0] = *(const float4*)(Ag + 64); ra[1] = *(const float4*)(Ag + 68);

    for (int k = 0; k < NK; k++) {
        if (k < NK - 1) { CP_WAIT(1); } else { CP_WAIT(0); }
        __syncthreads();
        const int cur = k % 3;
        __nv_bfloat16 (*Ah)[40] = AhB(cur);
        __nv_bfloat16 (*Al)[40] = AlB(cur);
        __nv_bfloat16 (*Bh)[40] = BhB(cur);
        __nv_bfloat16 (*Bl)[40] = BlB(cur);
        #pragma unroll
        for (int kk = 0; kk < 2; kk++) {
            const int kb = kk * 16;
            unsigned afh[2][4], afl[2][4];
            #pragma unroll
            for (int mt = 0; mt < 2; mt++) {
                ldm_x4(afh[mt], &Ah[wm * 32 + mt * 16 + (lane & 15)][kb + (lane >> 4) * 8]);
                ldm_x4(afl[mt], &Al[wm * 32 + mt * 16 + (lane & 15)][kb + (lane >> 4) * 8]);
            }
            #pragma unroll
            for (int ng = 0; ng < 2; ng++) {
                unsigned bfh[4], bfl[4];
                ldm_x4(bfh, &Bh[wn * 32 + ng * 16 + (lane & 15)][kb + (lane >> 4) * 8]);
                ldm_x4(bfl, &Bl[wn * 32 + ng * 16 + (lane & 15)][kb + (lane >> 4) * 8]);
                #pragma unroll
                for (int h = 0; h < 2; h++) {
                    const int nt = ng * 2 + h;
                    #pragma unroll
                    for (int mt = 0; mt < 2; mt++) {
                        mma_bf16(acc[mt][nt], afh[mt], bfh[h], bfh[2 + h]);
                        mma_bf16(acc[mt][nt], afh[mt], bfl[h], bfl[2 + h]);
                        mma_bf16(acc[mt][nt], afl[mt], bfh[h], bfh[2 + h]);
                    }
                }
            }
        }
        if (k + 2 < NK) {
            const int s = (k + 2) % 3;
            issueB((k + 2) * 32, s); CP_COMMIT();
            splitA((k + 2) * 32, s);
            if (k + 3 < NK) {
                ra[0] = *(const float4*)(Ag + (k + 3) * 32);
                ra[1] = *(const float4*)(Ag + (k + 3) * 32 + 4);
            }
        }
    }
    __syncthreads();

    a_part += __shfl_xor_sync(0xffffffffu, a_part, 1);
    a_part += __shfl_xor_sync(0xffffffffu, a_part, 2);
    if ((t & 3) == 0) sm_a[arow] = a_part;

    // stage accumulators into S (overlays ring buffers)
    #pragma unroll
    for (int mt = 0; mt < 2; mt++) {
        const int r0 = wm * 32 + mt * 16 + (lane >> 2);
        #pragma unroll
        for (int nt = 0; nt < 4; nt++) {
            const int q0 = wn * 32 + nt * 8 + (lane & 3) * 2;
            *(float2*)&S[r0 * SSTRIDE + q0]       = make_float2(acc[mt][nt][0], acc[mt][nt][1]);
            *(float2*)&S[(r0 + 8) * SSTRIDE + q0] = make_float2(acc[mt][nt][2], acc[mt][nt][3]);
        }
    }
    __syncthreads();

    float4 bq4 = *(const float4*)&sm_bq[lane * 4];
    #pragma unroll
    for (int r = 0; r < 8; r++) {
        const int row = wid * 8 + r;
        float4 v = *(const float4*)&S[row * SSTRIDE + lane * 4];
        float a = sm_a[row];
        v.x += a + bq4.x; v.y += a + bq4.y; v.z += a + bq4.z; v.w += a + bq4.w;
        float m = fmaxf(fmaxf(v.x, v.y), fmaxf(v.z, v.w));
        #pragma unroll
        for (int o = 16; o; o >>= 1) m = fmaxf(m, __shfl_xor_sync(0xffffffffu, m, o));
        *(float4*)(g_sim + ((size_t)(b * C + cb * 64 + row)) * Q + lane * 4) = v;
        if (lane == 0) g_smax[b * C + cb * 64 + row] = m;
    }
}

// ================= K2: fused middle (colstats || cweights+cdash) =================
__global__ __launch_bounds__(256) void k_mid(const float* __restrict__ cont,
                                             const int* __restrict__ qmask,
                                             const int* __restrict__ cmask) {
    __shared__ float sh_red[256];
    __shared__ float sh_w[512];
    const int t = threadIdx.x;

    if (blockIdx.x < 128) {
        // ---- colstats: b = id>>2, qt = id&3; threads 32 x 8 ----
        const int b = blockIdx.x >> 2;
        const int tx = t & 31, ty = t >> 5;
        const int q = (blockIdx.x & 3) * 32 + tx;
        const int qm = qmask[b * Q + q];
        float (*red)[32] = (float (*)[32])sh_red;
        float m = -3.4e38f;
        for (int c = ty; c < C; c += 8) {
            float v = g_sim[((size_t)(b * C + c)) * Q + q];
            m = fmaxf(m, qm ? v : NEGBIG);
        }
        red[ty][tx] = m;
        __syncthreads();
        if (ty == 0) {
            #pragma unroll
            for (int k = 1; k < 8; k++) m = fmaxf(m, red[k][tx]);
            red[0][tx] = m;
        }
        __syncthreads();
        m = red[0][tx];
        __syncthreads();
        float s = 0.f;
        for (int c = ty; c < C; c += 8) {
            float v = g_sim[((size_t)(b * C + c)) * Q + q];
            s += expf((qm ? v : NEGBIG) - m);
        }
        red[ty][tx] = s;
        __syncthreads();
        if (ty == 0) {
            #pragma unroll
            for (int k = 1; k < 8; k++) s += red[k][tx];
            red[0][tx] = 1.f / s;
        }
        __syncthreads();
        const float rs = red[0][tx];
        for (int c = ty; c < C; c += 8) {
            size_t idx = ((size_t)(b * C + c)) * Q + q;
            float v = g_sim[idx];
            float x = expf((qm ? v : NEGBIG) - m) * rs;
            __nv_bfloat16 h = __float2bfloat16(x);
            __nv_bfloat16 l = __float2bfloat16(x - __bfloat162float(h));
            g_Dh[idx] = h;
            g_Dl[idx] = l;
        }
    } else {
        // ---- cdash with inline weights: id = 0..383 -> (b, dchunk) ----
        const int id = blockIdx.x - 128;
        const int b = id / 12, dchunk = id % 12;
        // weights from g_smax (2 elems/thread)
        float s0 = g_smax[b * C + t], s1 = g_smax[b * C + 256 + t];
        float ms0 = cmask[b * C + t] ? s0 : NEGBIG;
        float ms1 = cmask[b * C + 256 + t] ? s1 : NEGBIG;
        sh_red[t] = fmaxf(ms0, ms1);
        __syncthreads();
        for (int o = 128; o; o >>= 1) {
            if (t < o) sh_red[t] = fmaxf(sh_red[t], sh_red[t + o]);
            __syncthreads();
        }
        float M = sh_red[0];
        __syncthreads();
        float e0 = expf(ms0 - M), e1 = expf(ms1 - M);
        sh_red[t] = e0 + e1;
        __syncthreads();
        for (int o = 128; o; o >>= 1) {
            if (t < o) sh_red[t] += sh_red[t + o];
            __syncthreads();
        }
        float rS = 1.f / sh_red[0];
        sh_w[t] = e0 * rS;
        sh_w[256 + t] = e1 * rS;
        __syncthreads();
        // cdash: 64 d x 4 c-strips
        const int d0 = dchunk * 64;
        const int dl = t & 63, cs = t >> 6;
        float acc = 0.f;
        const float* base = cont + ((size_t)(b * C + cs * 128)) * D + d0 + dl;
        const float* wp = &sh_w[cs * 128];
        #pragma unroll 4
        for (int c = 0; c < 128; c++) acc += wp[c] * base[(size_t)c * D];
        float (*red2)[64] = (float (*)[64])sh_red;
        red2[cs][dl] = acc;
        __syncthreads();
        if (t < 64)
            g_cdash[b * D + d0 + t] = (red2[0][t] + red2[1][t]) + (red2[2][t] + red2[3][t]);
    }
}

// ================= K3: c2q GEMM (3-stage cp.async) + epilogue =================
#define C2Q_STAGE 27648
#define C2Q_SMEM (3 * C2Q_STAGE)   // 82944
__global__ __launch_bounds__(256, 2) void k_c2q_mma(const float* __restrict__ cont,
                                                    float* __restrict__ out) {
    extern __shared__ char dbuf[];
    __shared__ float sm_cd[128];
    float* S = (float*)dbuf;

    const int cb = blockIdx.x, dt = blockIdx.y, b = blockIdx.z;
    const int t = threadIdx.x, lane = t & 31, wid = t >> 5;
    const int wm = wid & 1, wn = wid >> 1;

    if (t < 128) sm_cd[t] = g_cdash[b * D + dt * 128 + t];

    const __nv_bfloat16* Dh = g_Dh + ((size_t)(b * C + cb * 64)) * Q;
    const __nv_bfloat16* Dl = g_Dl + ((size_t)(b * C + cb * 64)) * Q;
    const __nv_bfloat16* Qh = g_Qh + ((size_t)b * Q) * D + dt * 128;
    const __nv_bfloat16* Ql = g_Ql + ((size_t)b * Q) * D + dt * 128;

    auto AhB = [&](int s) { return (__nv_bfloat16(*)[40])(dbuf + s * C2Q_STAGE); };
    auto AlB = [&](int s) { return (__nv_bfloat16(*)[40])(dbuf + s * C2Q_STAGE + 5120); };
    auto BhB = [&](int s) { return (__nv_bfloat16(*)[136])(dbuf + s * C2Q_STAGE + 10240); };
    auto BlB = [&](int s) { return (__nv_bfloat16(*)[136])(dbuf + s * C2Q_STAGE + 18944); };

    const int ar = t >> 2, acl = t & 3;
    auto issueChunk = [&](int k0, int s) {
        __nv_bfloat16 (*Ah)[40] = AhB(s);
        __nv_bfloat16 (*Al)[40] = AlB(s);
        cp16(&Ah[ar][acl * 8], Dh + (size_t)ar * Q + k0 + acl * 8);
        cp16(&Al[ar][acl * 8], Dl + (size_t)ar * Q + k0 + acl * 8);
        __nv_bfloat16 (*Bh)[136] = BhB(s);
        __nv_bfloat16 (*Bl)[136] = BlB(s);
        #pragma unroll
        for (int i = 0; i < 2; i++) {
            int idx = t + i * 256;
            int r = idx >> 4, cl = idx & 15;
            cp16(&Bh[r][cl * 8], Qh + (size_t)(k0 + r) * D + cl * 8);
            cp16(&Bl[r][cl * 8], Ql + (size_t)(k0 + r) * D + cl * 8);
        }
    };

    float acc[2][4][4];
    #pragma unroll
    for (int i = 0; i < 2; i++)
        #pragma unroll
        for (int j = 0; j < 4; j++)
            #pragma unroll
            for (int k = 0; k < 4; k++) acc[i][j][k] = 0.f;

    issueChunk(0, 0);  CP_COMMIT();
    issueChunk(32, 1); CP_COMMIT();

    #pragma unroll
    for (int k = 0; k < 4; k++) {
        if (k < 3) { CP_WAIT(1); } else { CP_WAIT(0); }
        __syncthreads();
        const int cur = k % 3;
        __nv_bfloat16 (*Ah)[40]  = AhB(cur);
        __nv_bfloat16 (*Al)[40]  = AlB(cur);
        __nv_bfloat16 (*Bh)[136] = BhB(cur);
        __nv_bfloat16 (*Bl)[136] = BlB(cur);
        #pragma unroll
        for (int kk = 0; kk < 2; kk++) {
            const int kb = kk * 16;
            unsigned afh[2][4], afl[2][4];
            #pragma unroll
            for (int mt = 0; mt < 2; mt++) {
                ldm_x4(afh[mt], &Ah[wm * 32 + mt * 16 + (lane & 15)][kb + (lane >> 4) * 8]);
                ldm_x4(afl[mt], &Al[wm * 32 + mt * 16 + (lane & 15)][kb + (lane >> 4) * 8]);
            }
            #pragma unroll
            for (int ng = 0; ng < 2; ng++) {
                unsigned bfh[4], bfl[4];
                ldm_x4t(bfh, &Bh[kb + (lane & 15)][wn * 32 + ng * 16 + (lane >> 4) * 8]);
                ldm_x4t(bfl, &Bl[kb + (lane & 15)][wn * 32 + ng * 16 + (lane >> 4) * 8]);
                #pragma unroll
                for (int h = 0; h < 2; h++) {
                    const int nt = ng * 2 + h;
                    #pragma unroll
                    for (int mt = 0; mt < 2; mt++) {
                        mma_bf16(acc[mt][nt], afh[mt], bfh[2 * h], bfh[2 * h + 1]);
                        mma_bf16(acc[mt][nt], afh[mt], bfl[2 * h], bfl[2 * h + 1]);
                        mma_bf16(acc[mt][nt], afl[mt], bfh[2 * h], bfh[2 * h + 1]);
                    }
                }
            }
        }
        if (k + 2 < 4) { issueChunk((k + 2) * 32, (k + 2) % 3); CP_COMMIT(); }
    }
    __syncthreads();

    // stage accumulators (S overlays ring buffers)
    #pragma unroll
    for (int mt = 0; mt < 2; mt++) {
        const int r0 = wm * 32 + mt * 16 + (lane >> 2);
        #pragma unroll
        for (int nt = 0; nt < 4; nt++) {
            const int d0 = wn * 32 + nt * 8 + (lane & 3) * 2;
            *(float2*)&S[r0 * SSTRIDE + d0]       = make_float2(acc[mt][nt][0], acc[mt][nt][1]);
            *(float2*)&S[(r0 + 8) * SSTRIDE + d0] = make_float2(acc[mt][nt][2], acc[mt][nt][3]);
        }
    }
    __syncthreads();

    float4 cd = *(const float4*)&sm_cd[lane * 4];
    #pragma unroll
    for (int r = 0; r < 8; r++) {
        const int row = wid * 8 + r;
        const int c = cb * 64 + row;
        float4 cq = *(const float4*)&S[row * SSTRIDE + lane * 4];
        float4 ct = *(const float4*)(cont + ((size_t)(b * C + c)) * D + dt * 128 + lane * 4);
        float4 m1 = make_float4(ct.x * cq.x, ct.y * cq.y, ct.z * cq.z, ct.w * cq.w);
        float4 m2 = make_float4(ct.x * cd.x, ct.y * cd.y, ct.z * cd.z, ct.w * cd.w);
        float* ob = out + ((size_t)(b * C + c)) * OD + dt * 128 + lane * 4;
        *(float4*)(ob)         = ct;
        *(float4*)(ob + D)     = cq;
        *(float4*)(ob + 2 * D) = m1;
        *(float4*)(ob + 3 * D) = m2;
    }
}

// ---------------- launch ----------------
extern "C" void kernel_launch(void* const* d_in, const int* in_sizes, int n_in,
                              void* d_out, int out_size) {
    const float* cont  = (const float*)d_in[0];
    const int*   cmask = (const int*)d_in[1];
    const float* ques  = (const float*)d_in[2];
    const int*   qmask = (const int*)d_in[3];
    const float* SW    = (const float*)d_in[4];
    float* out = (float*)d_out;
    (void)in_sizes; (void)n_in; (void)out_size;

    cudaFuncSetAttribute(k_sim_mma, cudaFuncAttributeMaxDynamicSharedMemorySize, SIM_SMEM);
    cudaFuncSetAttribute(k_c2q_mma, cudaFuncAttributeMaxDynamicSharedMemorySize, C2Q_SMEM);

    {                           k_convQ<<<B, 256>>>(ques, SW); }
    {   dim3 g(C / 64, B);      k_sim_mma<<<g, 256, SIM_SMEM>>>(cont, SW); }
    {                           k_mid<<<512, 256>>>(cont, qmask, cmask); }
    {   dim3 g(C / 64, 6, B);   k_c2q_mma<<<g, 256, C2Q_SMEM>>>(cont, out); }
}